// round 4
// baseline (speedup 1.0000x reference)
#include <cuda_runtime.h>
#include <math.h>

#define DEVF __device__ __forceinline__

// ---------------- problem constants ----------------
constexpr int HH = 512, WW = 512, NPIX = HH * WW, NC = 4;
constexpr int DBI = 5, DSP = 2;
constexpr int N_ITER = 10;

constexpr int BI_CAP = 1 << 22;
constexpr int SP_CAP = 1 << 21;
constexpr int BI_MMAX = NPIX * (DBI + 1); // 1,572,864
constexpr int SP_MMAX = NPIX * (DSP + 1); //   786,432
constexpr int BI_QUADS = BI_MMAX / 4;
constexpr int SP_QUADS = SP_MMAX / 4;
constexpr unsigned long long KEMPTY = ~0ull;

// ---------------- device scratch ----------------
__device__ unsigned long long g_bi_hk[BI_CAP];
__device__ unsigned long long g_sp_hk[SP_CAP];
__device__ int   g_bi_sid[BI_CAP];          // slot -> dense id (first-touch order)
__device__ int   g_sp_sid[SP_CAP];
__device__ unsigned long long g_bi_kl[BI_MMAX];
__device__ unsigned long long g_sp_kl[SP_MMAX];
__device__ int   g_bi_off[BI_MMAX];
__device__ int   g_sp_off[SP_MMAX];
__device__ float g_bi_ws[BI_MMAX];
__device__ float g_sp_ws[SP_MMAX];
__device__ __align__(16) int g_bi_bn[(DBI + 1) * BI_MMAX * 2];
__device__ __align__(16) int g_sp_bn[(DSP + 1) * SP_MMAX * 2];
// value buffers: A(0), B(1) ping-pong; C(2) = splat target. +1 zero-sentinel element.
__device__ __align__(16) float g_bi_vA[(BI_MMAX + 1) * NC];
__device__ __align__(16) float g_bi_vB[(BI_MMAX + 1) * NC];
__device__ __align__(16) float g_bi_vC[(BI_MMAX + 1) * NC];
__device__ __align__(16) float g_sp_vA[(SP_MMAX + 1) * NC];
__device__ __align__(16) float g_sp_vB[(SP_MMAX + 1) * NC];
__device__ __align__(16) float g_sp_vC[(SP_MMAX + 1) * NC];
__device__ float g_bi_nA[BI_MMAX + 1];
__device__ float g_bi_nB[BI_MMAX + 1];
__device__ float g_sp_nA[SP_MMAX + 1];
__device__ float g_sp_nB[SP_MMAX + 1];
__device__ float g_bi_norm[NPIX];
__device__ float g_sp_norm[NPIX];
__device__ int   g_bi_cnt, g_sp_cnt;

// ---------------- templated accessors ----------------
template<int D> DEVF unsigned long long* HK()  { return D == DBI ? g_bi_hk  : g_sp_hk;  }
template<int D> DEVF int*   SID()  { return D == DBI ? g_bi_sid : g_sp_sid; }
template<int D> DEVF unsigned long long* KL()  { return D == DBI ? g_bi_kl  : g_sp_kl;  }
template<int D> DEVF int*   OFFA() { return D == DBI ? g_bi_off : g_sp_off; }
template<int D> DEVF float* WSA()  { return D == DBI ? g_bi_ws  : g_sp_ws;  }
template<int D> DEVF int*   BNA()  { return D == DBI ? g_bi_bn  : g_sp_bn;  }
template<int D> DEVF int*   CNT()  { return D == DBI ? &g_bi_cnt: &g_sp_cnt;}
template<int D> DEVF int    CAPC() { return D == DBI ? BI_CAP   : SP_CAP;   }
template<int D> DEVF int    MMAXC(){ return D == DBI ? BI_MMAX  : SP_MMAX;  }
template<int D> DEVF int    KBITS(){ return D == DBI ? 8 : 10; }
template<int D> DEVF int    KBIAS(){ return D == DBI ? 128 : 512; }
template<int D> DEVF unsigned KMASK(){ return D == DBI ? 0xFFu : 0x3FFu; }

template<int D, int C> DEVF float* BUF3(int which) {
    if (C == 1) return D == DBI ? (which ? g_bi_nB : g_bi_nA) : (which ? g_sp_nB : g_sp_nA);
    if (D == DBI) return which == 2 ? g_bi_vC : (which ? g_bi_vB : g_bi_vA);
    return which == 2 ? g_sp_vC : (which ? g_sp_vB : g_sp_vA);
}

// vectorized float4 reduction (sm_90+)
DEVF void red4(float* p, float a, float b, float c, float d) {
    asm volatile("{ .reg .u64 pg; cvta.to.global.u64 pg, %0; "
                 "red.global.add.v4.f32 [pg], {%1,%2,%3,%4}; }"
                 :: "l"(p), "f"(a), "f"(b), "f"(c), "f"(d) : "memory");
}

// ---------------- hash ----------------
DEVF unsigned long long hmix(unsigned long long x) {
    x += 0x9E3779B97F4A7C15ull;
    x = (x ^ (x >> 30)) * 0xBF58476D1CE4E5B9ull;
    x = (x ^ (x >> 27)) * 0x94D049BB133111EBull;
    return x ^ (x >> 31);
}

// insert during build: winner claims dense id immediately (first-touch order)
template<int D>
DEVF int insert_slot(unsigned long long key) {
    const unsigned mask = (unsigned)(CAPC<D>() - 1);
    unsigned long long* hk = HK<D>();
    unsigned h = (unsigned)hmix(key) & mask;
    for (;;) {
        unsigned long long prev = atomicCAS(&hk[h], KEMPTY, key);
        if (prev == KEMPTY) {
            int id = atomicAdd(CNT<D>(), 1);
            SID<D>()[h] = id;
            KL<D>()[id] = key;
            return (int)h;
        }
        if (prev == key) return (int)h;
        h = (h + 1) & mask;
    }
}

// post-build lookup (hk holds raw keys; ids in SID)
template<int D>
DEVF int find_id(unsigned long long key) {
    const unsigned mask = (unsigned)(CAPC<D>() - 1);
    const unsigned long long* hk = HK<D>();
    unsigned h = (unsigned)hmix(key) & mask;
    for (;;) {
        unsigned long long v = hk[h];
        if (v == key) return SID<D>()[h];
        if (v == KEMPTY) return -1;
        h = (h + 1) & mask;
    }
}

// ---------------- kernels ----------------
template<int D>
__global__ void k_reset() {
    int i = blockIdx.x * blockDim.x + threadIdx.x;
    if (i >= CAPC<D>()) return;
    HK<D>()[i] = KEMPTY;
    if (i == 0) *CNT<D>() = 0;
}

template<int D>
__global__ void k_build(const float* __restrict__ x) {
    int i = blockIdx.x * blockDim.x + threadIdx.x;
    if (i >= NPIX) return;
    // 32x32 tile raster order for id locality
    int tile = i >> 10, within = i & 1023;
    int tx = within & 31, ty = within >> 5;
    int px = (tile & 15) * 32 + tx;
    int py = (tile >> 4) * 32 + ty;
    int n = py * WW + px;

    float fs[D];
    const double inv_std = sqrt(2.0 / 3.0) * (D + 1);
#pragma unroll
    for (int j = 0; j < D; j++) {
        float f;
        if (D == DBI) {
            if (j == 0)      f = __fdiv_rn((float)px, 80.0f);
            else if (j == 1) f = __fdiv_rn((float)py, 80.0f);
            else             f = __fdiv_rn(x[n * 7 + (6 - j)], 0.0625f);
        } else {
            f = __fdiv_rn((float)(j == 0 ? px : py), 3.0f);
        }
        float sc = (float)(1.0 / sqrt((j + 2.0) * (j + 1.0)) * inv_std);
        fs[j] = __fmul_rn(f, sc);
    }

    float elev[D + 1];
#pragma unroll
    for (int r = 0; r <= D; r++) {
        float s = 0.0f;
#pragma unroll
        for (int j = 0; j < D; j++) {
            float e = (r == 0) ? 1.0f : ((j == r - 1) ? -(float)r : (j >= r ? 1.0f : 0.0f));
            s = __fadd_rn(s, __fmul_rn(e, fs[j]));
        }
        elev[r] = s;
    }

    const float downf = __fdiv_rn(1.0f, (float)(D + 1));
    const float upf = (float)(D + 1);

    float rem0[D + 1], diff[D + 1];
    int   rnk[D + 1];
#pragma unroll
    for (int k = 0; k <= D; k++) {
        float v   = __fmul_rn(elev[k], downf);
        float upr = __fmul_rn(ceilf(v),  upf);
        float dnr = __fmul_rn(floorf(v), upf);
        rem0[k] = (__fsub_rn(upr, elev[k]) < __fsub_rn(elev[k], dnr)) ? upr : dnr;
    }
    float ssum = 0.0f;
#pragma unroll
    for (int k = 0; k <= D; k++) ssum = __fadd_rn(ssum, rem0[k]);
    int s = (int)__fmul_rn(ssum, downf);

#pragma unroll
    for (int k = 0; k <= D; k++) diff[k] = __fsub_rn(elev[k], rem0[k]);
#pragma unroll
    for (int k = 0; k <= D; k++) {
        int r = s;
#pragma unroll
        for (int j = 0; j <= D; j++) {
            if (j > k)      r += (diff[k] <  diff[j]);
            else if (j < k) r += (diff[j] >= diff[k]);
        }
        rnk[k] = r;
    }
#pragma unroll
    for (int k = 0; k <= D; k++) {
        if (rnk[k] < 0)      { rnk[k] += D + 1; rem0[k] = __fadd_rn(rem0[k], upf); }
        else if (rnk[k] > D) { rnk[k] -= D + 1; rem0[k] = __fsub_rn(rem0[k], upf); }
    }

    float b[D + 2];
#pragma unroll
    for (int k = 0; k < D + 2; k++) b[k] = 0.0f;
#pragma unroll
    for (int k = 0; k <= D; k++) {
        float vs = __fmul_rn(__fsub_rn(elev[k], rem0[k]), downf);
        int idx = D - rnk[k];
        b[idx]     = __fadd_rn(b[idx], vs);
        b[idx + 1] = __fsub_rn(b[idx + 1], vs);
    }
    b[0] = __fadd_rn(b[0], __fadd_rn(1.0f, b[D + 1]));

    int remi[D + 1];
#pragma unroll
    for (int k = 0; k <= D; k++) remi[k] = (int)rem0[k];

#pragma unroll
    for (int m = 0; m <= D; m++) {
        unsigned long long key = 0ull;
#pragma unroll
        for (int j = 0; j < D; j++) {
            int r  = rnk[j];
            int cm = (r < D + 1 - m) ? m : m - (D + 1);
            int c  = remi[j] + cm;
            key |= ((unsigned long long)((unsigned)(c + KBIAS<D>()) & KMASK<D>())) << (KBITS<D>() * j);
        }
        int slot = insert_slot<D>(key);
        OFFA<D>()[n * (D + 1) + m] = slot;
        WSA<D>()[n * (D + 1) + m]  = b[m];
    }
}

// slot -> dense id for both lattices
__global__ void k_fixoff() {
    int i = blockIdx.x * blockDim.x + threadIdx.x;
    if (i < BI_MMAX) g_bi_off[i] = g_bi_sid[g_bi_off[i]];
    else { int k = i - BI_MMAX; if (k < SP_MMAX) g_sp_off[k] = g_sp_sid[g_sp_off[k]]; }
}

template<int D>
__global__ void k_neigh() {
    int i = blockIdx.x * blockDim.x + threadIdx.x;
    if (i >= *CNT<D>()) return;
    unsigned long long key = KL<D>()[i];
    int c[D];
#pragma unroll
    for (int j = 0; j < D; j++) c[j] = (int)((key >> (KBITS<D>() * j)) & KMASK<D>()) - KBIAS<D>();
#pragma unroll
    for (int j = 0; j <= D; j++) {
        unsigned long long k1 = 0ull, k2 = 0ull;
#pragma unroll
        for (int t = 0; t < D; t++) {
            int add = (j < D && t == j) ? (D + 1) : 0;
            int c1 = c[t] - 1 + add;
            int c2 = c[t] + 1 - add;
            k1 |= ((unsigned long long)((unsigned)(c1 + KBIAS<D>()) & KMASK<D>())) << (KBITS<D>() * t);
            k2 |= ((unsigned long long)((unsigned)(c2 + KBIAS<D>()) & KMASK<D>())) << (KBITS<D>() * t);
        }
        int n1 = find_id<D>(k1), n2 = find_id<D>(k2);
        if (n1 < 0) n1 = MMAXC<D>();   // zero-sentinel
        if (n2 < 0) n2 = MMAXC<D>();
        ((int2*)BNA<D>())[j * MMAXC<D>() + i] = make_int2(n1, n2);
    }
}

// clear norm splat buffers (nA for both lattices)
__global__ void k_clearN() {
    int i = blockIdx.x * blockDim.x + threadIdx.x;
    if (i < BI_MMAX) { if (i < g_bi_cnt) g_bi_nA[i] = 0.0f; }
    else { int k = i - BI_MMAX; if (k < g_sp_cnt) g_sp_nA[k] = 0.0f; }
}

// one-time clear of splat (C) buffers, float4 stores
__global__ void k_clearC() {
    int i = blockIdx.x * blockDim.x + threadIdx.x;
    if (i < BI_MMAX) { if (i < g_bi_cnt) ((float4*)g_bi_vC)[i] = make_float4(0, 0, 0, 0); }
    else { int k = i - BI_MMAX; if (k < g_sp_cnt) ((float4*)g_sp_vC)[k] = make_float4(0, 0, 0, 0); }
}

// norm splat: both lattices in one kernel
__global__ void k_splatN() {
    int i = blockIdx.x * blockDim.x + threadIdx.x;
    if (i < BI_MMAX) atomicAdd(&g_bi_nA[g_bi_off[i]], g_bi_ws[i]);
    else { int k = i - BI_MMAX; if (k < SP_MMAX) atomicAdd(&g_sp_nA[g_sp_off[k]], g_sp_ws[k]); }
}

// blur a quad of points (i0..i0+3), i0 % 4 == 0; branchless via zero-sentinel
template<int D, int C, bool CLR>
DEVF void blur_quad(int i0, int axis, int inb, int outb) {
    int cnt = *CNT<D>();
    if (i0 >= cnt) return;
    const int2* bnA = ((const int2*)BNA<D>()) + axis * MMAXC<D>();
    int4 nq0 = *(const int4*)(bnA + i0);
    int4 nq1 = *(const int4*)(bnA + i0 + 2);
    int nbs[8] = { nq0.x, nq0.y, nq0.z, nq0.w, nq1.x, nq1.y, nq1.z, nq1.w };
    int nvalid = cnt - i0; if (nvalid > 4) nvalid = 4;
    if (C == 1) {
        const float* in = BUF3<D, 1>(inb);
        float* outp = BUF3<D, 1>(outb);
#pragma unroll
        for (int k = 0; k < 4; k++) {
            if (k < nvalid)
                outp[i0 + k] = in[i0 + k] + 0.5f * (in[nbs[2 * k]] + in[nbs[2 * k + 1]]);
        }
    } else {
        const float4* in = (const float4*)BUF3<D, C>(inb);
        float4* outp = (float4*)BUF3<D, C>(outb);
        float4* cb = (float4*)BUF3<D, C>(2);
#pragma unroll
        for (int k = 0; k < 4; k++) {
            if (k < nvalid) {
                float4 v = in[i0 + k];
                float4 a = in[nbs[2 * k]];
                float4 b = in[nbs[2 * k + 1]];
                v.x += 0.5f * (a.x + b.x); v.y += 0.5f * (a.y + b.y);
                v.z += 0.5f * (a.z + b.z); v.w += 0.5f * (a.w + b.w);
                outp[i0 + k] = v;
                if (CLR) cb[i0 + k] = make_float4(0, 0, 0, 0);
            }
        }
    }
}

// combined blur: bi quads first, then sp quads (when axis <= DSP)
template<int C, bool CLR>
__global__ void k_blur(int axis, int inb, int outb) {
    int t = blockIdx.x * blockDim.x + threadIdx.x;
    if (t < BI_QUADS) {
        blur_quad<DBI, C, CLR>(4 * t, axis, inb, outb);
    } else {
        int k = t - BI_QUADS;
        if (k < SP_QUADS) blur_quad<DSP, C, CLR>(4 * k, axis, inb, outb);
    }
}

// slice of norm filters (bi final in nA, sp final in nB)
__global__ void k_sliceN() {
    int n = blockIdx.x * blockDim.x + threadIdx.x;
    if (n >= NPIX) return;
    float sb = 0.0f, ss = 0.0f;
#pragma unroll
    for (int m = 0; m <= DBI; m++)
        sb += g_bi_ws[n * (DBI + 1) + m] * g_bi_nA[g_bi_off[n * (DBI + 1) + m]];
#pragma unroll
    for (int m = 0; m <= DSP; m++)
        ss += g_sp_ws[n * (DSP + 1) + m] * g_sp_nB[g_sp_off[n * (DSP + 1) + m]];
    g_bi_norm[n] = sb * (32.0f / 33.0f);
    g_sp_norm[n] = ss * 0.8f;
}

DEVF void splat_q(int n, float q0, float q1, float q2, float q3) {
#pragma unroll
    for (int m = 0; m <= DBI; m++) {
        int id  = g_bi_off[n * (DBI + 1) + m];
        float w = g_bi_ws[n * (DBI + 1) + m];
        red4(&g_bi_vC[id * 4], w * q0, w * q1, w * q2, w * q3);
    }
#pragma unroll
    for (int m = 0; m <= DSP; m++) {
        int id  = g_sp_off[n * (DSP + 1) + m];
        float w = g_sp_ws[n * (DSP + 1) + m];
        red4(&g_sp_vC[id * 4], w * q0, w * q1, w * q2, w * q3);
    }
}

__global__ void k_initQ(const float* __restrict__ logits) {
    int n = blockIdx.x * blockDim.x + threadIdx.x;
    if (n >= NPIX) return;
    float4 lg = ((const float4*)logits)[n];
    float mx = fmaxf(fmaxf(lg.x, lg.y), fmaxf(lg.z, lg.w));
    float e0 = expf(lg.x - mx), e1 = expf(lg.y - mx), e2 = expf(lg.z - mx), e3 = expf(lg.w - mx);
    float inv = 1.0f / (e0 + e1 + e2 + e3);
    splat_q(n, e0 * inv, e1 * inv, e2 * inv, e3 * inv);
}

template<bool LAST>
__global__ void k_update(const float* __restrict__ logits, float* __restrict__ out) {
    int n = blockIdx.x * blockDim.x + threadIdx.x;
    if (n >= NPIX) return;
    const float4* vb = (const float4*)g_bi_vA; // bi after 6 passes
    const float4* vs = (const float4*)g_sp_vB; // sp after 3 passes
    float ab0 = 0, ab1 = 0, ab2 = 0, ab3 = 0;
    float as0 = 0, as1 = 0, as2 = 0, as3 = 0;
#pragma unroll
    for (int m = 0; m <= DBI; m++) {
        int id  = g_bi_off[n * (DBI + 1) + m];
        float w = g_bi_ws[n * (DBI + 1) + m];
        float4 t = vb[id];
        ab0 += w * t.x; ab1 += w * t.y; ab2 += w * t.z; ab3 += w * t.w;
    }
#pragma unroll
    for (int m = 0; m <= DSP; m++) {
        int id  = g_sp_off[n * (DSP + 1) + m];
        float w = g_sp_ws[n * (DSP + 1) + m];
        float4 t = vs[id];
        as0 += w * t.x; as1 += w * t.y; as2 += w * t.z; as3 += w * t.w;
    }
    float fbi = 10.0f * (32.0f / 33.0f) / (g_bi_norm[n] + 1e-20f);
    float fsp = 3.0f * 0.8f / (g_sp_norm[n] + 1e-20f);
    float4 lg = ((const float4*)logits)[n];
    float a0 = lg.x + fbi * ab0 + fsp * as0;
    float a1 = lg.y + fbi * ab1 + fsp * as1;
    float a2 = lg.z + fbi * ab2 + fsp * as2;
    float a3 = lg.w + fbi * ab3 + fsp * as3;
    float mx = fmaxf(fmaxf(a0, a1), fmaxf(a2, a3));
    float e0 = expf(a0 - mx), e1 = expf(a1 - mx), e2 = expf(a2 - mx), e3 = expf(a3 - mx);
    float inv = 1.0f / (e0 + e1 + e2 + e3);
    float q0 = e0 * inv, q1 = e1 * inv, q2 = e2 * inv, q3 = e3 * inv;
    if (LAST) {
        ((float4*)out)[n] = make_float4(q0, q1, q2, q3);
    } else {
        splat_q(n, q0, q1, q2, q3);
    }
}

// ---------------- launch ----------------
extern "C" void kernel_launch(void* const* d_in, const int* in_sizes, int n_in,
                              void* d_out, int out_size) {
    (void)in_sizes; (void)n_in; (void)out_size;
    const float* x      = (const float*)d_in[0];
    const float* logits = (const float*)d_in[1];
    float* out = (float*)d_out;

    const int B = 256;
    auto g = [](long n) { return (unsigned)((n + 255) / 256); };
    const unsigned G_BOTH   = g(BI_MMAX + SP_MMAX);
    const unsigned G_BI     = g(BI_MMAX);
    const unsigned G_QUADS  = g(BI_QUADS + SP_QUADS);
    const unsigned G_QUADSB = g(BI_QUADS);
    const unsigned G_PIX    = g(NPIX);

    // ---- lattice construction ----
    k_reset<DBI><<<g(BI_CAP), B>>>();
    k_reset<DSP><<<g(SP_CAP), B>>>();
    k_build<DBI><<<G_PIX, B>>>(x);
    k_build<DSP><<<G_PIX, B>>>(x);
    k_fixoff<<<G_BOTH, B>>>();
    k_neigh<DBI><<<G_BI, B>>>();
    k_neigh<DSP><<<g(SP_MMAX), B>>>();

    // ---- normalization filters ----
    k_clearN<<<G_BOTH, B>>>();
    k_splatN<<<G_BOTH, B>>>();
    for (int j = 0; j <= DBI; j++) {
        unsigned grd = (j <= DSP) ? G_QUADS : G_QUADSB;
        k_blur<1, false><<<grd, B>>>(j, j & 1, (j & 1) ^ 1);
    }
    k_sliceN<<<G_PIX, B>>>();

    // ---- mean-field iterations ----
    k_clearC<<<G_BOTH, B>>>();
    k_initQ<<<G_PIX, B>>>(logits);
    for (int it = 0; it < N_ITER; it++) {
        for (int j = 0; j <= DBI; j++) {
            int inb  = (j == 0) ? 2 : (j & 1);
            int outb = (j & 1) ^ 1;
            unsigned grd = (j <= DSP) ? G_QUADS : G_QUADSB;
            if (j == 1)
                k_blur<NC, true><<<grd, B>>>(j, inb, outb);   // clears C inline
            else
                k_blur<NC, false><<<grd, B>>>(j, inb, outb);
        }
        if (it == N_ITER - 1)
            k_update<true><<<G_PIX, B>>>(logits, out);
        else
            k_update<false><<<G_PIX, B>>>(logits, out);
    }
}

// round 5
// speedup vs baseline: 1.0405x; 1.0405x over previous
#include <cuda_runtime.h>
#include <math.h>

#define DEVF __device__ __forceinline__

// ---------------- problem constants ----------------
constexpr int HH = 512, WW = 512, NPIX = HH * WW, NC = 4;
constexpr int DBI = 5, DSP = 2;
constexpr int N_ITER = 10;

constexpr int BI_CAP = 1 << 22;
constexpr int SP_CAP = 1 << 21;
constexpr int BI_MMAX = NPIX * (DBI + 1); // 1,572,864
constexpr int SP_MMAX = NPIX * (DSP + 1); //   786,432
constexpr int BI_PAIRS = BI_MMAX / 2;
constexpr int SP_PAIRS = SP_MMAX / 2;
constexpr unsigned long long KEMPTY = ~0ull;
constexpr unsigned long long M40 = (1ull << 40) - 1;

// ---------------- device scratch ----------------
__device__ unsigned long long g_bi_hk[BI_CAP];   // key (40b) | id<<40 after compact
__device__ unsigned long long g_sp_hk[SP_CAP];
__device__ unsigned long long g_bi_kl[BI_MMAX];
__device__ unsigned long long g_sp_kl[SP_MMAX];
__device__ int   g_bi_off[BI_MMAX];
__device__ int   g_sp_off[SP_MMAX];
__device__ float g_bi_ws[BI_MMAX];
__device__ float g_sp_ws[SP_MMAX];
__device__ __align__(16) int g_bi_bn[(DBI + 1) * BI_MMAX * 2];
__device__ __align__(16) int g_sp_bn[(DSP + 1) * SP_MMAX * 2];
// value buffers: A(0), B(1) ping-pong; C(2) = splat target. +1 zero-sentinel element at MMAX.
__device__ __align__(16) float g_bi_vA[(BI_MMAX + 1) * NC];
__device__ __align__(16) float g_bi_vB[(BI_MMAX + 1) * NC];
__device__ __align__(16) float g_bi_vC[(BI_MMAX + 1) * NC];
__device__ __align__(16) float g_sp_vA[(SP_MMAX + 1) * NC];
__device__ __align__(16) float g_sp_vB[(SP_MMAX + 1) * NC];
__device__ __align__(16) float g_sp_vC[(SP_MMAX + 1) * NC];
__device__ float g_bi_nA[BI_MMAX + 1];
__device__ float g_bi_nB[BI_MMAX + 1];
__device__ float g_sp_nA[SP_MMAX + 1];
__device__ float g_sp_nB[SP_MMAX + 1];
__device__ float g_bi_norm[NPIX];
__device__ float g_sp_norm[NPIX];
__device__ int   g_bi_cnt, g_sp_cnt;

// ---------------- templated accessors ----------------
template<int D> DEVF unsigned long long* HK()  { return D == DBI ? g_bi_hk  : g_sp_hk;  }
template<int D> DEVF unsigned long long* KL()  { return D == DBI ? g_bi_kl  : g_sp_kl;  }
template<int D> DEVF int*   OFFA() { return D == DBI ? g_bi_off : g_sp_off; }
template<int D> DEVF float* WSA()  { return D == DBI ? g_bi_ws  : g_sp_ws;  }
template<int D> DEVF int*   BNA()  { return D == DBI ? g_bi_bn  : g_sp_bn;  }
template<int D> DEVF int*   CNT()  { return D == DBI ? &g_bi_cnt: &g_sp_cnt;}
template<int D> DEVF int    CAPC() { return D == DBI ? BI_CAP   : SP_CAP;   }
template<int D> DEVF int    MMAXC(){ return D == DBI ? BI_MMAX  : SP_MMAX;  }
template<int D> DEVF int    KBITS(){ return D == DBI ? 8 : 10; }
template<int D> DEVF int    KBIAS(){ return D == DBI ? 128 : 512; }
template<int D> DEVF unsigned KMASK(){ return D == DBI ? 0xFFu : 0x3FFu; }

template<int D, int C> DEVF float* BUF3(int which) {
    if (C == 1) return D == DBI ? (which ? g_bi_nB : g_bi_nA) : (which ? g_sp_nB : g_sp_nA);
    if (D == DBI) return which == 2 ? g_bi_vC : (which ? g_bi_vB : g_bi_vA);
    return which == 2 ? g_sp_vC : (which ? g_sp_vB : g_sp_vA);
}

// vectorized float4 reduction (sm_90+)
DEVF void red4(float* p, float a, float b, float c, float d) {
    asm volatile("{ .reg .u64 pg; cvta.to.global.u64 pg, %0; "
                 "red.global.add.v4.f32 [pg], {%1,%2,%3,%4}; }"
                 :: "l"(p), "f"(a), "f"(b), "f"(c), "f"(d) : "memory");
}

// ---------------- hash ----------------
DEVF unsigned long long hmix(unsigned long long x) {
    x += 0x9E3779B97F4A7C15ull;
    x = (x ^ (x >> 30)) * 0xBF58476D1CE4E5B9ull;
    x = (x ^ (x >> 27)) * 0x94D049BB133111EBull;
    return x ^ (x >> 31);
}

template<int D>
DEVF int insert_slot(unsigned long long key) {
    const unsigned mask = (unsigned)(CAPC<D>() - 1);
    unsigned long long* hk = HK<D>();
    unsigned h = (unsigned)hmix(key) & mask;
    for (;;) {
        unsigned long long prev = atomicCAS(&hk[h], KEMPTY, key);
        if (prev == KEMPTY || prev == key) return (int)h;
        h = (h + 1) & mask;
    }
}

// post-compact lookup: single 8B random read per probe, id in high bits
template<int D>
DEVF int find_id(unsigned long long key) {
    const unsigned mask = (unsigned)(CAPC<D>() - 1);
    const unsigned long long* hk = HK<D>();
    unsigned h = (unsigned)hmix(key) & mask;
    for (;;) {
        unsigned long long v = hk[h];
        if (v == KEMPTY) return -1;
        if ((v & M40) == key) return (int)(v >> 40);
        h = (h + 1) & mask;
    }
}

// ---------------- kernels ----------------
template<int D>
__global__ void k_reset() {
    int i = blockIdx.x * blockDim.x + threadIdx.x;
    if (i >= CAPC<D>()) return;
    HK<D>()[i] = KEMPTY;
    if (i == 0) *CNT<D>() = 0;
}

template<int D>
__global__ void k_build(const float* __restrict__ x) {
    int n = blockIdx.x * blockDim.x + threadIdx.x;
    if (n >= NPIX) return;
    int py = n / WW, px = n - py * WW;

    float fs[D];
    const double inv_std = sqrt(2.0 / 3.0) * (D + 1);
#pragma unroll
    for (int j = 0; j < D; j++) {
        float f;
        if (D == DBI) {
            if (j == 0)      f = __fdiv_rn((float)px, 80.0f);
            else if (j == 1) f = __fdiv_rn((float)py, 80.0f);
            else             f = __fdiv_rn(x[n * 7 + (6 - j)], 0.0625f);
        } else {
            f = __fdiv_rn((float)(j == 0 ? px : py), 3.0f);
        }
        float sc = (float)(1.0 / sqrt((j + 2.0) * (j + 1.0)) * inv_std);
        fs[j] = __fmul_rn(f, sc);
    }

    float elev[D + 1];
#pragma unroll
    for (int r = 0; r <= D; r++) {
        float s = 0.0f;
#pragma unroll
        for (int j = 0; j < D; j++) {
            float e = (r == 0) ? 1.0f : ((j == r - 1) ? -(float)r : (j >= r ? 1.0f : 0.0f));
            s = __fadd_rn(s, __fmul_rn(e, fs[j]));
        }
        elev[r] = s;
    }

    const float downf = __fdiv_rn(1.0f, (float)(D + 1));
    const float upf = (float)(D + 1);

    float rem0[D + 1], diff[D + 1];
    int   rnk[D + 1];
#pragma unroll
    for (int k = 0; k <= D; k++) {
        float v   = __fmul_rn(elev[k], downf);
        float upr = __fmul_rn(ceilf(v),  upf);
        float dnr = __fmul_rn(floorf(v), upf);
        rem0[k] = (__fsub_rn(upr, elev[k]) < __fsub_rn(elev[k], dnr)) ? upr : dnr;
    }
    float ssum = 0.0f;
#pragma unroll
    for (int k = 0; k <= D; k++) ssum = __fadd_rn(ssum, rem0[k]);
    int s = (int)__fmul_rn(ssum, downf);

#pragma unroll
    for (int k = 0; k <= D; k++) diff[k] = __fsub_rn(elev[k], rem0[k]);
#pragma unroll
    for (int k = 0; k <= D; k++) {
        int r = s;
#pragma unroll
        for (int j = 0; j <= D; j++) {
            if (j > k)      r += (diff[k] <  diff[j]);
            else if (j < k) r += (diff[j] >= diff[k]);
        }
        rnk[k] = r;
    }
#pragma unroll
    for (int k = 0; k <= D; k++) {
        if (rnk[k] < 0)      { rnk[k] += D + 1; rem0[k] = __fadd_rn(rem0[k], upf); }
        else if (rnk[k] > D) { rnk[k] -= D + 1; rem0[k] = __fsub_rn(rem0[k], upf); }
    }

    float b[D + 2];
#pragma unroll
    for (int k = 0; k < D + 2; k++) b[k] = 0.0f;
#pragma unroll
    for (int k = 0; k <= D; k++) {
        float vs = __fmul_rn(__fsub_rn(elev[k], rem0[k]), downf);
        int idx = D - rnk[k];
        b[idx]     = __fadd_rn(b[idx], vs);
        b[idx + 1] = __fsub_rn(b[idx + 1], vs);
    }
    b[0] = __fadd_rn(b[0], __fadd_rn(1.0f, b[D + 1]));

    int remi[D + 1];
#pragma unroll
    for (int k = 0; k <= D; k++) remi[k] = (int)rem0[k];

#pragma unroll
    for (int m = 0; m <= D; m++) {
        unsigned long long key = 0ull;
#pragma unroll
        for (int j = 0; j < D; j++) {
            int r  = rnk[j];
            int cm = (r < D + 1 - m) ? m : m - (D + 1);
            int c  = remi[j] + cm;
            key |= ((unsigned long long)((unsigned)(c + KBIAS<D>()) & KMASK<D>())) << (KBITS<D>() * j);
        }
        int slot = insert_slot<D>(key);
        OFFA<D>()[n * (D + 1) + m] = slot;
        WSA<D>()[n * (D + 1) + m]  = b[m];
    }
}

template<int D>
__global__ void k_compact() {
    int i = blockIdx.x * blockDim.x + threadIdx.x;
    if (i >= CAPC<D>()) return;
    unsigned long long k = HK<D>()[i];
    if (k != KEMPTY) {
        int id = atomicAdd(CNT<D>(), 1);
        HK<D>()[i] = k | ((unsigned long long)id << 40);
        KL<D>()[id] = k;
    }
}

template<int D>
__global__ void k_fixoff() {
    int i = blockIdx.x * blockDim.x + threadIdx.x;
    if (i >= NPIX * (D + 1)) return;
    OFFA<D>()[i] = (int)(HK<D>()[OFFA<D>()[i]] >> 40);
}

template<int D>
__global__ void k_neigh() {
    int i = blockIdx.x * blockDim.x + threadIdx.x;
    if (i >= *CNT<D>()) return;
    unsigned long long key = KL<D>()[i];
    int c[D];
#pragma unroll
    for (int j = 0; j < D; j++) c[j] = (int)((key >> (KBITS<D>() * j)) & KMASK<D>()) - KBIAS<D>();
#pragma unroll
    for (int j = 0; j <= D; j++) {
        unsigned long long k1 = 0ull, k2 = 0ull;
#pragma unroll
        for (int t = 0; t < D; t++) {
            int add = (j < D && t == j) ? (D + 1) : 0;
            int c1 = c[t] - 1 + add;
            int c2 = c[t] + 1 - add;
            k1 |= ((unsigned long long)((unsigned)(c1 + KBIAS<D>()) & KMASK<D>())) << (KBITS<D>() * t);
            k2 |= ((unsigned long long)((unsigned)(c2 + KBIAS<D>()) & KMASK<D>())) << (KBITS<D>() * t);
        }
        int n1 = find_id<D>(k1), n2 = find_id<D>(k2);
        if (n1 < 0) n1 = MMAXC<D>();   // zero-sentinel
        if (n2 < 0) n2 = MMAXC<D>();
        ((int2*)BNA<D>())[j * MMAXC<D>() + i] = make_int2(n1, n2);
    }
}

// clear norm splat buffers (nA for both lattices)
__global__ void k_clearN() {
    int i = blockIdx.x * blockDim.x + threadIdx.x;
    if (i < BI_MMAX) { if (i < g_bi_cnt) g_bi_nA[i] = 0.0f; }
    else { int k = i - BI_MMAX; if (k < g_sp_cnt) g_sp_nA[k] = 0.0f; }
}

// one-time clear of splat (C) buffers, float4 stores
__global__ void k_clearC() {
    int i = blockIdx.x * blockDim.x + threadIdx.x;
    if (i < BI_MMAX) { if (i < g_bi_cnt) ((float4*)g_bi_vC)[i] = make_float4(0, 0, 0, 0); }
    else { int k = i - BI_MMAX; if (k < g_sp_cnt) ((float4*)g_sp_vC)[k] = make_float4(0, 0, 0, 0); }
}

// norm splat: both lattices in one kernel
__global__ void k_splatN() {
    int i = blockIdx.x * blockDim.x + threadIdx.x;
    if (i < BI_MMAX) atomicAdd(&g_bi_nA[g_bi_off[i]], g_bi_ws[i]);
    else { int k = i - BI_MMAX; if (k < SP_MMAX) atomicAdd(&g_sp_nA[g_sp_off[k]], g_sp_ws[k]); }
}

// blur a pair of points (i, i+1), i even; branchless gathers via zero-sentinel
template<int D, int C, bool CLR>
DEVF void blur_pair(int i, int axis, int inb, int outb) {
    int cnt = *CNT<D>();
    if (i >= cnt) return;
    const int2* bnA = ((const int2*)BNA<D>()) + axis * MMAXC<D>();
    int4 nbp = *(const int4*)(bnA + i);          // neighbors of i (x,y) and i+1 (z,w)
    bool two = (i + 1 < cnt);
    if (C == 1) {
        const float* in = BUF3<D, 1>(inb);
        float* outp = BUF3<D, 1>(outb);
        float a0 = in[nbp.x], b0 = in[nbp.y];
        float v0 = in[i];
        outp[i] = v0 + 0.5f * (a0 + b0);
        if (two) {
            float a1 = in[nbp.z], b1 = in[nbp.w];
            outp[i + 1] = in[i + 1] + 0.5f * (a1 + b1);
        }
    } else {
        const float4* in = (const float4*)BUF3<D, C>(inb);
        float4* outp = (float4*)BUF3<D, C>(outb);
        float4 v0 = in[i];
        float4 a0 = in[nbp.x];
        float4 b0 = in[nbp.y];
        v0.x += 0.5f * (a0.x + b0.x); v0.y += 0.5f * (a0.y + b0.y);
        v0.z += 0.5f * (a0.z + b0.z); v0.w += 0.5f * (a0.w + b0.w);
        outp[i] = v0;
        if (two) {
            float4 v1 = in[i + 1];
            float4 a1 = in[nbp.z];
            float4 b1 = in[nbp.w];
            v1.x += 0.5f * (a1.x + b1.x); v1.y += 0.5f * (a1.y + b1.y);
            v1.z += 0.5f * (a1.z + b1.z); v1.w += 0.5f * (a1.w + b1.w);
            outp[i + 1] = v1;
        }
        if (CLR) {
            float4* cb = (float4*)BUF3<D, C>(2);
            cb[i] = make_float4(0, 0, 0, 0);
            if (two) cb[i + 1] = make_float4(0, 0, 0, 0);
        }
    }
}

// combined blur: bi pairs first, then sp pairs (when axis <= DSP)
template<int C, bool CLR>
__global__ void k_blur(int axis, int inb, int outb) {
    int t = blockIdx.x * blockDim.x + threadIdx.x;
    if (t < BI_PAIRS) {
        blur_pair<DBI, C, CLR>(2 * t, axis, inb, outb);
    } else {
        int k = t - BI_PAIRS;
        if (k < SP_PAIRS) blur_pair<DSP, C, CLR>(2 * k, axis, inb, outb);
    }
}

// slice of norm filters (bi final in nA, sp final in nB)
__global__ void k_sliceN() {
    int n = blockIdx.x * blockDim.x + threadIdx.x;
    if (n >= NPIX) return;
    float sb = 0.0f, ss = 0.0f;
#pragma unroll
    for (int m = 0; m <= DBI; m++)
        sb += g_bi_ws[n * (DBI + 1) + m] * g_bi_nA[g_bi_off[n * (DBI + 1) + m]];
#pragma unroll
    for (int m = 0; m <= DSP; m++)
        ss += g_sp_ws[n * (DSP + 1) + m] * g_sp_nB[g_sp_off[n * (DSP + 1) + m]];
    g_bi_norm[n] = sb * (32.0f / 33.0f);
    g_sp_norm[n] = ss * 0.8f;
}

DEVF void splat_q(int n, float q0, float q1, float q2, float q3) {
#pragma unroll
    for (int m = 0; m <= DBI; m++) {
        int id  = g_bi_off[n * (DBI + 1) + m];
        float w = g_bi_ws[n * (DBI + 1) + m];
        red4(&g_bi_vC[id * 4], w * q0, w * q1, w * q2, w * q3);
    }
#pragma unroll
    for (int m = 0; m <= DSP; m++) {
        int id  = g_sp_off[n * (DSP + 1) + m];
        float w = g_sp_ws[n * (DSP + 1) + m];
        red4(&g_sp_vC[id * 4], w * q0, w * q1, w * q2, w * q3);
    }
}

__global__ void k_initQ(const float* __restrict__ logits) {
    int n = blockIdx.x * blockDim.x + threadIdx.x;
    if (n >= NPIX) return;
    float4 lg = ((const float4*)logits)[n];
    float mx = fmaxf(fmaxf(lg.x, lg.y), fmaxf(lg.z, lg.w));
    float e0 = expf(lg.x - mx), e1 = expf(lg.y - mx), e2 = expf(lg.z - mx), e3 = expf(lg.w - mx);
    float inv = 1.0f / (e0 + e1 + e2 + e3);
    splat_q(n, e0 * inv, e1 * inv, e2 * inv, e3 * inv);
}

template<bool LAST>
__global__ void k_update(const float* __restrict__ logits, float* __restrict__ out) {
    int n = blockIdx.x * blockDim.x + threadIdx.x;
    if (n >= NPIX) return;
    const float4* vb = (const float4*)g_bi_vA; // bi after 6 passes (C->B->A->B->A->B->A)
    const float4* vs = (const float4*)g_sp_vB; // sp after 3 passes (C->B->A->B)
    float ab0 = 0, ab1 = 0, ab2 = 0, ab3 = 0;
    float as0 = 0, as1 = 0, as2 = 0, as3 = 0;
#pragma unroll
    for (int m = 0; m <= DBI; m++) {
        int id  = g_bi_off[n * (DBI + 1) + m];
        float w = g_bi_ws[n * (DBI + 1) + m];
        float4 t = vb[id];
        ab0 += w * t.x; ab1 += w * t.y; ab2 += w * t.z; ab3 += w * t.w;
    }
#pragma unroll
    for (int m = 0; m <= DSP; m++) {
        int id  = g_sp_off[n * (DSP + 1) + m];
        float w = g_sp_ws[n * (DSP + 1) + m];
        float4 t = vs[id];
        as0 += w * t.x; as1 += w * t.y; as2 += w * t.z; as3 += w * t.w;
    }
    float fbi = 10.0f * (32.0f / 33.0f) / (g_bi_norm[n] + 1e-20f);
    float fsp = 3.0f * 0.8f / (g_sp_norm[n] + 1e-20f);
    float4 lg = ((const float4*)logits)[n];
    float a0 = lg.x + fbi * ab0 + fsp * as0;
    float a1 = lg.y + fbi * ab1 + fsp * as1;
    float a2 = lg.z + fbi * ab2 + fsp * as2;
    float a3 = lg.w + fbi * ab3 + fsp * as3;
    float mx = fmaxf(fmaxf(a0, a1), fmaxf(a2, a3));
    float e0 = expf(a0 - mx), e1 = expf(a1 - mx), e2 = expf(a2 - mx), e3 = expf(a3 - mx);
    float inv = 1.0f / (e0 + e1 + e2 + e3);
    float q0 = e0 * inv, q1 = e1 * inv, q2 = e2 * inv, q3 = e3 * inv;
    if (LAST) {
        ((float4*)out)[n] = make_float4(q0, q1, q2, q3);
    } else {
        splat_q(n, q0, q1, q2, q3);
    }
}

// ---------------- launch ----------------
extern "C" void kernel_launch(void* const* d_in, const int* in_sizes, int n_in,
                              void* d_out, int out_size) {
    (void)in_sizes; (void)n_in; (void)out_size;
    const float* x      = (const float*)d_in[0];
    const float* logits = (const float*)d_in[1];
    float* out = (float*)d_out;

    const int B = 256;
    auto g = [](long n) { return (unsigned)((n + 255) / 256); };
    const unsigned G_BOTH   = g(BI_MMAX + SP_MMAX);
    const unsigned G_BI     = g(BI_MMAX);
    const unsigned G_PAIRS  = g(BI_PAIRS + SP_PAIRS);
    const unsigned G_PAIRSB = g(BI_PAIRS);
    const unsigned G_PIX    = g(NPIX);

    // ---- lattice construction ----
    k_reset<DBI><<<g(BI_CAP), B>>>();
    k_reset<DSP><<<g(SP_CAP), B>>>();
    k_build<DBI><<<G_PIX, B>>>(x);
    k_build<DSP><<<G_PIX, B>>>(x);
    k_compact<DBI><<<g(BI_CAP), B>>>();
    k_compact<DSP><<<g(SP_CAP), B>>>();
    k_fixoff<DBI><<<G_BI, B>>>();
    k_fixoff<DSP><<<g(SP_MMAX), B>>>();
    k_neigh<DBI><<<G_BI, B>>>();
    k_neigh<DSP><<<g(SP_MMAX), B>>>();

    // ---- normalization filters ----
    k_clearN<<<G_BOTH, B>>>();
    k_splatN<<<G_BOTH, B>>>();
    for (int j = 0; j <= DBI; j++) {
        unsigned grd = (j <= DSP) ? G_PAIRS : G_PAIRSB;
        k_blur<1, false><<<grd, B>>>(j, j & 1, (j & 1) ^ 1);
    }
    k_sliceN<<<G_PIX, B>>>();

    // ---- mean-field iterations ----
    k_clearC<<<G_BOTH, B>>>();
    k_initQ<<<G_PIX, B>>>(logits);
    for (int it = 0; it < N_ITER; it++) {
        for (int j = 0; j <= DBI; j++) {
            int inb  = (j == 0) ? 2 : (j & 1);
            int outb = (j & 1) ^ 1;
            unsigned grd = (j <= DSP) ? G_PAIRS : G_PAIRSB;
            if (j == 1)
                k_blur<NC, true><<<grd, B>>>(j, inb, outb);   // clears C inline
            else
                k_blur<NC, false><<<grd, B>>>(j, inb, outb);
        }
        if (it == N_ITER - 1)
            k_update<true><<<G_PIX, B>>>(logits, out);
        else
            k_update<false><<<G_PIX, B>>>(logits, out);
    }
}

// round 6
// speedup vs baseline: 1.1398x; 1.0955x over previous
#include <cuda_runtime.h>
#include <math.h>

#define DEVF __device__ __forceinline__

// ---------------- problem constants ----------------
constexpr int HH = 512, WW = 512, NPIX = HH * WW, NC = 4;
constexpr int DBI = 5, DSP = 2;
constexpr int N_ITER = 10;

constexpr int BI_CAP = 1 << 22;
constexpr int SP_CAP = 1 << 21;
constexpr int BI_MMAX = NPIX * (DBI + 1); // 1,572,864
constexpr int SP_MMAX = NPIX * (DSP + 1); //   786,432
constexpr int BI_PAIRS = BI_MMAX / 2;
constexpr int SP_PAIRS = SP_MMAX / 2;
constexpr int NBKT = 1024;               // 32x32 tiles of 16x16 pixels
constexpr unsigned long long KEMPTY = ~0ull;
constexpr unsigned long long M40 = (1ull << 40) - 1;

// ---------------- device scratch ----------------
__device__ unsigned long long g_bi_hk[BI_CAP];   // key (40b) | id<<40 after assign
__device__ unsigned long long g_sp_hk[SP_CAP];
__device__ int   g_bi_bkt[BI_CAP];               // slot -> tile bucket (winner's tile)
__device__ int   g_sp_bkt[SP_CAP];
__device__ int   g_hist[2 * NBKT];               // [0,NBKT)=bi, [NBKT,2*NBKT)=sp
__device__ unsigned long long g_bi_kl[BI_MMAX];
__device__ unsigned long long g_sp_kl[SP_MMAX];
__device__ int   g_bi_off[BI_MMAX];
__device__ int   g_sp_off[SP_MMAX];
__device__ float g_bi_ws[BI_MMAX];
__device__ float g_sp_ws[SP_MMAX];
__device__ __align__(16) int g_bi_bn[(DBI + 1) * BI_MMAX * 2];
__device__ __align__(16) int g_sp_bn[(DSP + 1) * SP_MMAX * 2];
// value buffers: A(0), B(1) ping-pong; C(2) = splat target
__device__ __align__(16) float g_bi_vA[BI_MMAX * NC];
__device__ __align__(16) float g_bi_vB[BI_MMAX * NC];
__device__ __align__(16) float g_bi_vC[BI_MMAX * NC];
__device__ __align__(16) float g_sp_vA[SP_MMAX * NC];
__device__ __align__(16) float g_sp_vB[SP_MMAX * NC];
__device__ __align__(16) float g_sp_vC[SP_MMAX * NC];
__device__ float g_bi_nA[BI_MMAX];
__device__ float g_bi_nB[BI_MMAX];
__device__ float g_sp_nA[SP_MMAX];
__device__ float g_sp_nB[SP_MMAX];
__device__ float g_bi_norm[NPIX];
__device__ float g_sp_norm[NPIX];
__device__ int   g_bi_cnt, g_sp_cnt;

// ---------------- templated accessors ----------------
template<int D> DEVF unsigned long long* HK()  { return D == DBI ? g_bi_hk  : g_sp_hk;  }
template<int D> DEVF int*   BKT()  { return D == DBI ? g_bi_bkt : g_sp_bkt; }
template<int D> DEVF unsigned long long* KL()  { return D == DBI ? g_bi_kl  : g_sp_kl;  }
template<int D> DEVF int*   OFFA() { return D == DBI ? g_bi_off : g_sp_off; }
template<int D> DEVF float* WSA()  { return D == DBI ? g_bi_ws  : g_sp_ws;  }
template<int D> DEVF int*   BNA()  { return D == DBI ? g_bi_bn  : g_sp_bn;  }
template<int D> DEVF int*   CNT()  { return D == DBI ? &g_bi_cnt: &g_sp_cnt;}
template<int D> DEVF int    CAPC() { return D == DBI ? BI_CAP   : SP_CAP;   }
template<int D> DEVF int    MMAXC(){ return D == DBI ? BI_MMAX  : SP_MMAX;  }
template<int D> DEVF int    KBITS(){ return D == DBI ? 8 : 10; }
template<int D> DEVF int    KBIAS(){ return D == DBI ? 128 : 512; }
template<int D> DEVF unsigned KMASK(){ return D == DBI ? 0xFFu : 0x3FFu; }

template<int D, int C> DEVF float* BUF3(int which) {
    if (C == 1) return D == DBI ? (which ? g_bi_nB : g_bi_nA) : (which ? g_sp_nB : g_sp_nA);
    if (D == DBI) return which == 2 ? g_bi_vC : (which ? g_bi_vB : g_bi_vA);
    return which == 2 ? g_sp_vC : (which ? g_sp_vB : g_sp_vA);
}

// vectorized float4 reduction (sm_90+)
DEVF void red4(float* p, float a, float b, float c, float d) {
    asm volatile("{ .reg .u64 pg; cvta.to.global.u64 pg, %0; "
                 "red.global.add.v4.f32 [pg], {%1,%2,%3,%4}; }"
                 :: "l"(p), "f"(a), "f"(b), "f"(c), "f"(d) : "memory");
}

// ---------------- hash ----------------
DEVF unsigned long long hmix(unsigned long long x) {
    x += 0x9E3779B97F4A7C15ull;
    x = (x ^ (x >> 30)) * 0xBF58476D1CE4E5B9ull;
    x = (x ^ (x >> 27)) * 0x94D049BB133111EBull;
    return x ^ (x >> 31);
}

// insert during build: CAS winner records its pixel-tile bucket
template<int D>
DEVF int insert_slot(unsigned long long key, int bkt) {
    const unsigned mask = (unsigned)(CAPC<D>() - 1);
    unsigned long long* hk = HK<D>();
    unsigned h = (unsigned)hmix(key) & mask;
    for (;;) {
        unsigned long long prev = atomicCAS(&hk[h], KEMPTY, key);
        if (prev == KEMPTY) { BKT<D>()[h] = bkt; return (int)h; }
        if (prev == key) return (int)h;
        h = (h + 1) & mask;
    }
}

// post-assign lookup: single 8B random read per probe, id in high bits
template<int D>
DEVF int find_id(unsigned long long key) {
    const unsigned mask = (unsigned)(CAPC<D>() - 1);
    const unsigned long long* hk = HK<D>();
    unsigned h = (unsigned)hmix(key) & mask;
    for (;;) {
        unsigned long long v = hk[h];
        if (v == KEMPTY) return -1;
        if ((v & M40) == key) return (int)(v >> 40);
        h = (h + 1) & mask;
    }
}

// ---------------- kernels ----------------
template<int D>
__global__ void k_reset() {
    int i = blockIdx.x * blockDim.x + threadIdx.x;
    if (i >= CAPC<D>()) return;
    HK<D>()[i] = KEMPTY;
    if (D == DBI && i < 2 * NBKT) g_hist[i] = 0;
}

template<int D>
__global__ void k_build(const float* __restrict__ x) {
    int n = blockIdx.x * blockDim.x + threadIdx.x;
    if (n >= NPIX) return;
    int py = n / WW, px = n - py * WW;
    int bkt = ((py >> 4) << 5) | (px >> 4);   // 16x16 pixel tile id

    float fs[D];
    const double inv_std = sqrt(2.0 / 3.0) * (D + 1);
#pragma unroll
    for (int j = 0; j < D; j++) {
        float f;
        if (D == DBI) {
            if (j == 0)      f = __fdiv_rn((float)px, 80.0f);
            else if (j == 1) f = __fdiv_rn((float)py, 80.0f);
            else             f = __fdiv_rn(x[n * 7 + (6 - j)], 0.0625f);
        } else {
            f = __fdiv_rn((float)(j == 0 ? px : py), 3.0f);
        }
        float sc = (float)(1.0 / sqrt((j + 2.0) * (j + 1.0)) * inv_std);
        fs[j] = __fmul_rn(f, sc);
    }

    float elev[D + 1];
#pragma unroll
    for (int r = 0; r <= D; r++) {
        float s = 0.0f;
#pragma unroll
        for (int j = 0; j < D; j++) {
            float e = (r == 0) ? 1.0f : ((j == r - 1) ? -(float)r : (j >= r ? 1.0f : 0.0f));
            s = __fadd_rn(s, __fmul_rn(e, fs[j]));
        }
        elev[r] = s;
    }

    const float downf = __fdiv_rn(1.0f, (float)(D + 1));
    const float upf = (float)(D + 1);

    float rem0[D + 1], diff[D + 1];
    int   rnk[D + 1];
#pragma unroll
    for (int k = 0; k <= D; k++) {
        float v   = __fmul_rn(elev[k], downf);
        float upr = __fmul_rn(ceilf(v),  upf);
        float dnr = __fmul_rn(floorf(v), upf);
        rem0[k] = (__fsub_rn(upr, elev[k]) < __fsub_rn(elev[k], dnr)) ? upr : dnr;
    }
    float ssum = 0.0f;
#pragma unroll
    for (int k = 0; k <= D; k++) ssum = __fadd_rn(ssum, rem0[k]);
    int s = (int)__fmul_rn(ssum, downf);

#pragma unroll
    for (int k = 0; k <= D; k++) diff[k] = __fsub_rn(elev[k], rem0[k]);
#pragma unroll
    for (int k = 0; k <= D; k++) {
        int r = s;
#pragma unroll
        for (int j = 0; j <= D; j++) {
            if (j > k)      r += (diff[k] <  diff[j]);
            else if (j < k) r += (diff[j] >= diff[k]);
        }
        rnk[k] = r;
    }
#pragma unroll
    for (int k = 0; k <= D; k++) {
        if (rnk[k] < 0)      { rnk[k] += D + 1; rem0[k] = __fadd_rn(rem0[k], upf); }
        else if (rnk[k] > D) { rnk[k] -= D + 1; rem0[k] = __fsub_rn(rem0[k], upf); }
    }

    float b[D + 2];
#pragma unroll
    for (int k = 0; k < D + 2; k++) b[k] = 0.0f;
#pragma unroll
    for (int k = 0; k <= D; k++) {
        float vs = __fmul_rn(__fsub_rn(elev[k], rem0[k]), downf);
        int idx = D - rnk[k];
        b[idx]     = __fadd_rn(b[idx], vs);
        b[idx + 1] = __fsub_rn(b[idx + 1], vs);
    }
    b[0] = __fadd_rn(b[0], __fadd_rn(1.0f, b[D + 1]));

    int remi[D + 1];
#pragma unroll
    for (int k = 0; k <= D; k++) remi[k] = (int)rem0[k];

#pragma unroll
    for (int m = 0; m <= D; m++) {
        unsigned long long key = 0ull;
#pragma unroll
        for (int j = 0; j < D; j++) {
            int r  = rnk[j];
            int cm = (r < D + 1 - m) ? m : m - (D + 1);
            int c  = remi[j] + cm;
            key |= ((unsigned long long)((unsigned)(c + KBIAS<D>()) & KMASK<D>())) << (KBITS<D>() * j);
        }
        int slot = insert_slot<D>(key, bkt);
        OFFA<D>()[n * (D + 1) + m] = slot;
        WSA<D>()[n * (D + 1) + m]  = b[m];
    }
}

// histogram of occupied slots per bucket (both lattices)
__global__ void k_hist() {
    int i = blockIdx.x * blockDim.x + threadIdx.x;
    if (i < BI_CAP) {
        if (g_bi_hk[i] != KEMPTY) atomicAdd(&g_hist[g_bi_bkt[i]], 1);
    } else {
        int k = i - BI_CAP;
        if (k < SP_CAP && g_sp_hk[k] != KEMPTY) atomicAdd(&g_hist[NBKT + g_sp_bkt[k]], 1);
    }
}

// exclusive scan of both histograms (1 block, NBKT threads); leaves running
// bases in g_hist for k_assign's atomicAdd; writes total counts
__global__ void k_scan() {
    __shared__ int sh[NBKT];
    int t = threadIdx.x;
    int v0 = g_hist[t];
    sh[t] = v0; __syncthreads();
#pragma unroll
    for (int o = 1; o < NBKT; o <<= 1) {
        int v = (t >= o) ? sh[t - o] : 0; __syncthreads();
        sh[t] += v; __syncthreads();
    }
    g_hist[t] = sh[t] - v0;            // exclusive base
    if (t == NBKT - 1) g_bi_cnt = sh[NBKT - 1];
    __syncthreads();
    int v1 = g_hist[NBKT + t];
    sh[t] = v1; __syncthreads();
#pragma unroll
    for (int o = 1; o < NBKT; o <<= 1) {
        int v = (t >= o) ? sh[t - o] : 0; __syncthreads();
        sh[t] += v; __syncthreads();
    }
    g_hist[NBKT + t] = sh[t] - v1;
    if (t == NBKT - 1) g_sp_cnt = sh[NBKT - 1];
}

// assign bucketed dense ids; embed in hash slot high bits; fill key list
__global__ void k_assign() {
    int i = blockIdx.x * blockDim.x + threadIdx.x;
    if (i < BI_CAP) {
        unsigned long long k = g_bi_hk[i];
        if (k != KEMPTY) {
            int id = atomicAdd(&g_hist[g_bi_bkt[i]], 1);
            g_bi_hk[i] = k | ((unsigned long long)id << 40);
            g_bi_kl[id] = k;
        }
    } else {
        int j = i - BI_CAP;
        if (j < SP_CAP) {
            unsigned long long k = g_sp_hk[j];
            if (k != KEMPTY) {
                int id = atomicAdd(&g_hist[NBKT + g_sp_bkt[j]], 1);
                g_sp_hk[j] = k | ((unsigned long long)id << 40);
                g_sp_kl[id] = k;
            }
        }
    }
}

// slot -> dense id for both lattices
__global__ void k_fixoff() {
    int i = blockIdx.x * blockDim.x + threadIdx.x;
    if (i < BI_MMAX) g_bi_off[i] = (int)(g_bi_hk[g_bi_off[i]] >> 40);
    else { int k = i - BI_MMAX; if (k < SP_MMAX) g_sp_off[k] = (int)(g_sp_hk[g_sp_off[k]] >> 40); }
}

template<int D>
__global__ void k_neigh() {
    int i = blockIdx.x * blockDim.x + threadIdx.x;
    if (i >= *CNT<D>()) return;
    unsigned long long key = KL<D>()[i];
    int c[D];
#pragma unroll
    for (int j = 0; j < D; j++) c[j] = (int)((key >> (KBITS<D>() * j)) & KMASK<D>()) - KBIAS<D>();
#pragma unroll
    for (int j = 0; j <= D; j++) {
        unsigned long long k1 = 0ull, k2 = 0ull;
#pragma unroll
        for (int t = 0; t < D; t++) {
            int add = (j < D && t == j) ? (D + 1) : 0;
            int c1 = c[t] - 1 + add;
            int c2 = c[t] + 1 - add;
            k1 |= ((unsigned long long)((unsigned)(c1 + KBIAS<D>()) & KMASK<D>())) << (KBITS<D>() * t);
            k2 |= ((unsigned long long)((unsigned)(c2 + KBIAS<D>()) & KMASK<D>())) << (KBITS<D>() * t);
        }
        ((int2*)BNA<D>())[j * MMAXC<D>() + i] = make_int2(find_id<D>(k1), find_id<D>(k2));
    }
}

// clear norm splat buffers (nA for both lattices)
__global__ void k_clearN() {
    int i = blockIdx.x * blockDim.x + threadIdx.x;
    if (i < BI_MMAX) { if (i < g_bi_cnt) g_bi_nA[i] = 0.0f; }
    else { int k = i - BI_MMAX; if (k < g_sp_cnt) g_sp_nA[k] = 0.0f; }
}

// one-time clear of splat (C) buffers, float4 stores
__global__ void k_clearC() {
    int i = blockIdx.x * blockDim.x + threadIdx.x;
    if (i < BI_MMAX) { if (i < g_bi_cnt) ((float4*)g_bi_vC)[i] = make_float4(0, 0, 0, 0); }
    else { int k = i - BI_MMAX; if (k < g_sp_cnt) ((float4*)g_sp_vC)[k] = make_float4(0, 0, 0, 0); }
}

// norm splat: both lattices in one kernel
__global__ void k_splatN() {
    int i = blockIdx.x * blockDim.x + threadIdx.x;
    if (i < BI_MMAX) atomicAdd(&g_bi_nA[g_bi_off[i]], g_bi_ws[i]);
    else { int k = i - BI_MMAX; if (k < SP_MMAX) atomicAdd(&g_sp_nA[g_sp_off[k]], g_sp_ws[k]); }
}

// blur a pair of points (i, i+1), i even; predicated gathers (-1 = missing)
template<int D, int C, bool CLR>
DEVF void blur_pair(int i, int axis, int inb, int outb) {
    int cnt = *CNT<D>();
    if (i >= cnt) return;
    const int2* bnA = ((const int2*)BNA<D>()) + axis * MMAXC<D>();
    int4 nbp = *(const int4*)(bnA + i);          // neighbors of i (x,y) and i+1 (z,w)
    bool two = (i + 1 < cnt);
    if (C == 1) {
        const float* in = BUF3<D, 1>(inb);
        float* outp = BUF3<D, 1>(outb);
        float s0 = 0.0f;
        if (nbp.x >= 0) s0 += in[nbp.x];
        if (nbp.y >= 0) s0 += in[nbp.y];
        outp[i] = in[i] + 0.5f * s0;
        if (two) {
            float s1 = 0.0f;
            if (nbp.z >= 0) s1 += in[nbp.z];
            if (nbp.w >= 0) s1 += in[nbp.w];
            outp[i + 1] = in[i + 1] + 0.5f * s1;
        }
    } else {
        const float4* in = (const float4*)BUF3<D, C>(inb);
        float4* outp = (float4*)BUF3<D, C>(outb);
        float4 v0 = in[i];
        float4 a0 = make_float4(0, 0, 0, 0), b0 = a0;
        if (nbp.x >= 0) a0 = in[nbp.x];
        if (nbp.y >= 0) b0 = in[nbp.y];
        v0.x += 0.5f * (a0.x + b0.x); v0.y += 0.5f * (a0.y + b0.y);
        v0.z += 0.5f * (a0.z + b0.z); v0.w += 0.5f * (a0.w + b0.w);
        outp[i] = v0;
        if (two) {
            float4 v1 = in[i + 1];
            float4 a1 = make_float4(0, 0, 0, 0), b1 = a1;
            if (nbp.z >= 0) a1 = in[nbp.z];
            if (nbp.w >= 0) b1 = in[nbp.w];
            v1.x += 0.5f * (a1.x + b1.x); v1.y += 0.5f * (a1.y + b1.y);
            v1.z += 0.5f * (a1.z + b1.z); v1.w += 0.5f * (a1.w + b1.w);
            outp[i + 1] = v1;
        }
        if (CLR) {
            float4* cb = (float4*)BUF3<D, C>(2);
            cb[i] = make_float4(0, 0, 0, 0);
            if (two) cb[i + 1] = make_float4(0, 0, 0, 0);
        }
    }
}

// combined blur: bi pairs first, then sp pairs (when axis <= DSP)
template<int C, bool CLR>
__global__ void k_blur(int axis, int inb, int outb) {
    int t = blockIdx.x * blockDim.x + threadIdx.x;
    if (t < BI_PAIRS) {
        blur_pair<DBI, C, CLR>(2 * t, axis, inb, outb);
    } else {
        int k = t - BI_PAIRS;
        if (k < SP_PAIRS) blur_pair<DSP, C, CLR>(2 * k, axis, inb, outb);
    }
}

// slice of norm filters (bi final in nA, sp final in nB)
__global__ void k_sliceN() {
    int n = blockIdx.x * blockDim.x + threadIdx.x;
    if (n >= NPIX) return;
    float sb = 0.0f, ss = 0.0f;
#pragma unroll
    for (int m = 0; m <= DBI; m++)
        sb += g_bi_ws[n * (DBI + 1) + m] * g_bi_nA[g_bi_off[n * (DBI + 1) + m]];
#pragma unroll
    for (int m = 0; m <= DSP; m++)
        ss += g_sp_ws[n * (DSP + 1) + m] * g_sp_nB[g_sp_off[n * (DSP + 1) + m]];
    g_bi_norm[n] = sb * (32.0f / 33.0f);
    g_sp_norm[n] = ss * 0.8f;
}

DEVF void splat_q(int n, float q0, float q1, float q2, float q3) {
#pragma unroll
    for (int m = 0; m <= DBI; m++) {
        int id  = g_bi_off[n * (DBI + 1) + m];
        float w = g_bi_ws[n * (DBI + 1) + m];
        red4(&g_bi_vC[id * 4], w * q0, w * q1, w * q2, w * q3);
    }
#pragma unroll
    for (int m = 0; m <= DSP; m++) {
        int id  = g_sp_off[n * (DSP + 1) + m];
        float w = g_sp_ws[n * (DSP + 1) + m];
        red4(&g_sp_vC[id * 4], w * q0, w * q1, w * q2, w * q3);
    }
}

__global__ void k_initQ(const float* __restrict__ logits) {
    int n = blockIdx.x * blockDim.x + threadIdx.x;
    if (n >= NPIX) return;
    float4 lg = ((const float4*)logits)[n];
    float mx = fmaxf(fmaxf(lg.x, lg.y), fmaxf(lg.z, lg.w));
    float e0 = expf(lg.x - mx), e1 = expf(lg.y - mx), e2 = expf(lg.z - mx), e3 = expf(lg.w - mx);
    float inv = 1.0f / (e0 + e1 + e2 + e3);
    splat_q(n, e0 * inv, e1 * inv, e2 * inv, e3 * inv);
}

template<bool LAST>
__global__ void k_update(const float* __restrict__ logits, float* __restrict__ out) {
    int n = blockIdx.x * blockDim.x + threadIdx.x;
    if (n >= NPIX) return;
    const float4* vb = (const float4*)g_bi_vA; // bi after 6 passes (C->B->A->B->A->B->A)
    const float4* vs = (const float4*)g_sp_vB; // sp after 3 passes (C->B->A->B)
    float ab0 = 0, ab1 = 0, ab2 = 0, ab3 = 0;
    float as0 = 0, as1 = 0, as2 = 0, as3 = 0;
#pragma unroll
    for (int m = 0; m <= DBI; m++) {
        int id  = g_bi_off[n * (DBI + 1) + m];
        float w = g_bi_ws[n * (DBI + 1) + m];
        float4 t = vb[id];
        ab0 += w * t.x; ab1 += w * t.y; ab2 += w * t.z; ab3 += w * t.w;
    }
#pragma unroll
    for (int m = 0; m <= DSP; m++) {
        int id  = g_sp_off[n * (DSP + 1) + m];
        float w = g_sp_ws[n * (DSP + 1) + m];
        float4 t = vs[id];
        as0 += w * t.x; as1 += w * t.y; as2 += w * t.z; as3 += w * t.w;
    }
    float fbi = 10.0f * (32.0f / 33.0f) / (g_bi_norm[n] + 1e-20f);
    float fsp = 3.0f * 0.8f / (g_sp_norm[n] + 1e-20f);
    float4 lg = ((const float4*)logits)[n];
    float a0 = lg.x + fbi * ab0 + fsp * as0;
    float a1 = lg.y + fbi * ab1 + fsp * as1;
    float a2 = lg.z + fbi * ab2 + fsp * as2;
    float a3 = lg.w + fbi * ab3 + fsp * as3;
    float mx = fmaxf(fmaxf(a0, a1), fmaxf(a2, a3));
    float e0 = expf(a0 - mx), e1 = expf(a1 - mx), e2 = expf(a2 - mx), e3 = expf(a3 - mx);
    float inv = 1.0f / (e0 + e1 + e2 + e3);
    float q0 = e0 * inv, q1 = e1 * inv, q2 = e2 * inv, q3 = e3 * inv;
    if (LAST) {
        ((float4*)out)[n] = make_float4(q0, q1, q2, q3);
    } else {
        splat_q(n, q0, q1, q2, q3);
    }
}

// ---------------- launch ----------------
extern "C" void kernel_launch(void* const* d_in, const int* in_sizes, int n_in,
                              void* d_out, int out_size) {
    (void)in_sizes; (void)n_in; (void)out_size;
    const float* x      = (const float*)d_in[0];
    const float* logits = (const float*)d_in[1];
    float* out = (float*)d_out;

    const int B = 256;
    auto g = [](long n) { return (unsigned)((n + 255) / 256); };
    const unsigned G_BOTH   = g(BI_MMAX + SP_MMAX);
    const unsigned G_BI     = g(BI_MMAX);
    const unsigned G_CAPS   = g(BI_CAP + SP_CAP);
    const unsigned G_PAIRS  = g(BI_PAIRS + SP_PAIRS);
    const unsigned G_PAIRSB = g(BI_PAIRS);
    const unsigned G_PIX    = g(NPIX);

    // ---- lattice construction ----
    k_reset<DBI><<<g(BI_CAP), B>>>();
    k_reset<DSP><<<g(SP_CAP), B>>>();
    k_build<DBI><<<G_PIX, B>>>(x);
    k_build<DSP><<<G_PIX, B>>>(x);
    k_hist<<<G_CAPS, B>>>();
    k_scan<<<1, NBKT>>>();
    k_assign<<<G_CAPS, B>>>();
    k_fixoff<<<G_BOTH, B>>>();
    k_neigh<DBI><<<G_BI, B>>>();
    k_neigh<DSP><<<g(SP_MMAX), B>>>();

    // ---- normalization filters ----
    k_clearN<<<G_BOTH, B>>>();
    k_splatN<<<G_BOTH, B>>>();
    for (int j = 0; j <= DBI; j++) {
        unsigned grd = (j <= DSP) ? G_PAIRS : G_PAIRSB;
        k_blur<1, false><<<grd, B>>>(j, j & 1, (j & 1) ^ 1);
    }
    k_sliceN<<<G_PIX, B>>>();

    // ---- mean-field iterations ----
    k_clearC<<<G_BOTH, B>>>();
    k_initQ<<<G_PIX, B>>>(logits);
    for (int it = 0; it < N_ITER; it++) {
        for (int j = 0; j <= DBI; j++) {
            int inb  = (j == 0) ? 2 : (j & 1);
            int outb = (j & 1) ^ 1;
            unsigned grd = (j <= DSP) ? G_PAIRS : G_PAIRSB;
            if (j == 1)
                k_blur<NC, true><<<grd, B>>>(j, inb, outb);   // clears C inline
            else
                k_blur<NC, false><<<grd, B>>>(j, inb, outb);
        }
        if (it == N_ITER - 1)
            k_update<true><<<G_PIX, B>>>(logits, out);
        else
            k_update<false><<<G_PIX, B>>>(logits, out);
    }
}

// round 7
// speedup vs baseline: 1.2136x; 1.0648x over previous
#include <cuda_runtime.h>
#include <math.h>

#define DEVF __device__ __forceinline__

// ---------------- problem constants ----------------
constexpr int HH = 512, WW = 512, NPIX = HH * WW, NC = 4;
constexpr int DBI = 5, DSP = 2;
constexpr int N_ITER = 10;

constexpr int BI_CAP = 1 << 22;
constexpr int SP_CAP = 1 << 19;          // spatial lattice is data-independent, ~<50K points
constexpr int BI_MMAX = NPIX * (DBI + 1); // 1,572,864
constexpr int SP_MMAX = NPIX * (DSP + 1); //   786,432
constexpr int BI_PAIRS = BI_MMAX / 2;
constexpr int SP_PAIRS = SP_MMAX / 2;
constexpr int NBKT = 1024;               // 32x32 tiles of 16x16 pixels
constexpr unsigned long long KEMPTY = ~0ull;
constexpr unsigned long long M40 = (1ull << 40) - 1;
constexpr float ALPHA_BI = 32.0f / 33.0f;
constexpr float ALPHA_SP = 0.8f;

// ---------------- device scratch ----------------
__device__ unsigned long long g_bi_hk[BI_CAP];   // key (40b) | id<<40 after assign
__device__ unsigned long long g_sp_hk[SP_CAP];
__device__ int   g_bi_bkt[BI_CAP];               // slot -> tile bucket (winner's tile)
__device__ int   g_sp_bkt[SP_CAP];
__device__ int   g_hist[2 * NBKT];               // [0,NBKT)=bi, [NBKT,2*NBKT)=sp
__device__ unsigned long long g_bi_kl[BI_MMAX];
__device__ unsigned long long g_sp_kl[SP_MMAX];
__device__ int   g_bi_off[BI_MMAX];
__device__ int   g_sp_off[SP_MMAX];
__device__ float g_bi_ws[BI_MMAX];
__device__ float g_sp_ws[SP_MMAX];
__device__ __align__(16) int g_bi_bn[(DBI + 1) * BI_MMAX * 2];
__device__ __align__(16) int g_sp_bn[(DSP + 1) * SP_MMAX * 2];
// value buffers: A(0), B(1) ping-pong; C(2) = splat target
__device__ __align__(16) float g_bi_vA[BI_MMAX * NC];
__device__ __align__(16) float g_bi_vB[BI_MMAX * NC];
__device__ __align__(16) float g_bi_vC[BI_MMAX * NC];
__device__ __align__(16) float g_sp_vA[SP_MMAX * NC];
__device__ __align__(16) float g_sp_vB[SP_MMAX * NC];
__device__ __align__(16) float g_sp_vC[SP_MMAX * NC];
__device__ float g_bi_nA[BI_MMAX];
__device__ float g_bi_nB[BI_MMAX];
__device__ float g_sp_nA[SP_MMAX];
__device__ float g_sp_nB[SP_MMAX];
__device__ float g_bi_norm[NPIX];
__device__ float g_sp_norm[NPIX];
__device__ int   g_bi_cnt, g_sp_cnt;

// ---------------- templated accessors ----------------
template<int D> DEVF unsigned long long* HK()  { return D == DBI ? g_bi_hk  : g_sp_hk;  }
template<int D> DEVF int*   BKT()  { return D == DBI ? g_bi_bkt : g_sp_bkt; }
template<int D> DEVF unsigned long long* KL()  { return D == DBI ? g_bi_kl  : g_sp_kl;  }
template<int D> DEVF int*   OFFA() { return D == DBI ? g_bi_off : g_sp_off; }
template<int D> DEVF float* WSA()  { return D == DBI ? g_bi_ws  : g_sp_ws;  }
template<int D> DEVF int*   BNA()  { return D == DBI ? g_bi_bn  : g_sp_bn;  }
template<int D> DEVF int*   CNT()  { return D == DBI ? &g_bi_cnt: &g_sp_cnt;}
template<int D> DEVF int    CAPC() { return D == DBI ? BI_CAP   : SP_CAP;   }
template<int D> DEVF int    MMAXC(){ return D == DBI ? BI_MMAX  : SP_MMAX;  }
template<int D> DEVF int    KBITS(){ return D == DBI ? 8 : 10; }
template<int D> DEVF int    KBIAS(){ return D == DBI ? 128 : 512; }
template<int D> DEVF unsigned KMASK(){ return D == DBI ? 0xFFu : 0x3FFu; }
template<int D> DEVF int    HBASE(){ return D == DBI ? 0 : NBKT; }

// which==0 -> A, 1 -> B, 2 -> C (value float4 buffers); norm variant has A/B only
template<int D> DEVF float* VBUF(int which) {
    if (D == DBI) return which == 2 ? g_bi_vC : (which ? g_bi_vB : g_bi_vA);
    return which == 2 ? g_sp_vC : (which ? g_sp_vB : g_sp_vA);
}
template<int D> DEVF float* NBUF(int which) {
    return D == DBI ? (which ? g_bi_nB : g_bi_nA) : (which ? g_sp_nB : g_sp_nA);
}

// vectorized float4 reduction (sm_90+)
DEVF void red4(float* p, float a, float b, float c, float d) {
    asm volatile("{ .reg .u64 pg; cvta.to.global.u64 pg, %0; "
                 "red.global.add.v4.f32 [pg], {%1,%2,%3,%4}; }"
                 :: "l"(p), "f"(a), "f"(b), "f"(c), "f"(d) : "memory");
}
DEVF void red1(float* p, float a) {
    asm volatile("{ .reg .u64 pg; cvta.to.global.u64 pg, %0; "
                 "red.global.add.f32 [pg], %1; }"
                 :: "l"(p), "f"(a) : "memory");
}

// ---------------- hash ----------------
DEVF unsigned long long hmix(unsigned long long x) {
    x += 0x9E3779B97F4A7C15ull;
    x = (x ^ (x >> 30)) * 0xBF58476D1CE4E5B9ull;
    x = (x ^ (x >> 27)) * 0x94D049BB133111EBull;
    return x ^ (x >> 31);
}

// insert during build: CAS winner records bucket + bumps histogram
template<int D>
DEVF int insert_slot(unsigned long long key, int bkt) {
    const unsigned mask = (unsigned)(CAPC<D>() - 1);
    unsigned long long* hk = HK<D>();
    unsigned h = (unsigned)hmix(key) & mask;
    for (;;) {
        unsigned long long prev = atomicCAS(&hk[h], KEMPTY, key);
        if (prev == KEMPTY) {
            BKT<D>()[h] = bkt;
            atomicAdd(&g_hist[HBASE<D>() + bkt], 1);
            return (int)h;
        }
        if (prev == key) return (int)h;
        h = (h + 1) & mask;
    }
}

// post-assign lookup: single 8B random read per probe, id in high bits
template<int D>
DEVF int find_id(unsigned long long key) {
    const unsigned mask = (unsigned)(CAPC<D>() - 1);
    const unsigned long long* hk = HK<D>();
    unsigned h = (unsigned)hmix(key) & mask;
    for (;;) {
        unsigned long long v = hk[h];
        if (v == KEMPTY) return -1;
        if ((v & M40) == key) return (int)(v >> 40);
        h = (h + 1) & mask;
    }
}

// ---------------- kernels ----------------
template<int D>
__global__ void k_reset() {
    int i = blockIdx.x * blockDim.x + threadIdx.x;
    if (i >= CAPC<D>()) return;
    HK<D>()[i] = KEMPTY;
    if (D == DBI && i < 2 * NBKT) g_hist[i] = 0;
}

template<int D>
__global__ void k_build(const float* __restrict__ x) {
    int n = blockIdx.x * blockDim.x + threadIdx.x;
    if (n >= NPIX) return;
    int py = n / WW, px = n - py * WW;
    int bkt = ((py >> 4) << 5) | (px >> 4);   // 16x16 pixel tile id

    float fs[D];
    const double inv_std = sqrt(2.0 / 3.0) * (D + 1);
#pragma unroll
    for (int j = 0; j < D; j++) {
        float f;
        if (D == DBI) {
            if (j == 0)      f = __fdiv_rn((float)px, 80.0f);
            else if (j == 1) f = __fdiv_rn((float)py, 80.0f);
            else             f = __fdiv_rn(x[n * 7 + (6 - j)], 0.0625f);
        } else {
            f = __fdiv_rn((float)(j == 0 ? px : py), 3.0f);
        }
        float sc = (float)(1.0 / sqrt((j + 2.0) * (j + 1.0)) * inv_std);
        fs[j] = __fmul_rn(f, sc);
    }

    float elev[D + 1];
#pragma unroll
    for (int r = 0; r <= D; r++) {
        float s = 0.0f;
#pragma unroll
        for (int j = 0; j < D; j++) {
            float e = (r == 0) ? 1.0f : ((j == r - 1) ? -(float)r : (j >= r ? 1.0f : 0.0f));
            s = __fadd_rn(s, __fmul_rn(e, fs[j]));
        }
        elev[r] = s;
    }

    const float downf = __fdiv_rn(1.0f, (float)(D + 1));
    const float upf = (float)(D + 1);

    float rem0[D + 1], diff[D + 1];
    int   rnk[D + 1];
#pragma unroll
    for (int k = 0; k <= D; k++) {
        float v   = __fmul_rn(elev[k], downf);
        float upr = __fmul_rn(ceilf(v),  upf);
        float dnr = __fmul_rn(floorf(v), upf);
        rem0[k] = (__fsub_rn(upr, elev[k]) < __fsub_rn(elev[k], dnr)) ? upr : dnr;
    }
    float ssum = 0.0f;
#pragma unroll
    for (int k = 0; k <= D; k++) ssum = __fadd_rn(ssum, rem0[k]);
    int s = (int)__fmul_rn(ssum, downf);

#pragma unroll
    for (int k = 0; k <= D; k++) diff[k] = __fsub_rn(elev[k], rem0[k]);
#pragma unroll
    for (int k = 0; k <= D; k++) {
        int r = s;
#pragma unroll
        for (int j = 0; j <= D; j++) {
            if (j > k)      r += (diff[k] <  diff[j]);
            else if (j < k) r += (diff[j] >= diff[k]);
        }
        rnk[k] = r;
    }
#pragma unroll
    for (int k = 0; k <= D; k++) {
        if (rnk[k] < 0)      { rnk[k] += D + 1; rem0[k] = __fadd_rn(rem0[k], upf); }
        else if (rnk[k] > D) { rnk[k] -= D + 1; rem0[k] = __fsub_rn(rem0[k], upf); }
    }

    float b[D + 2];
#pragma unroll
    for (int k = 0; k < D + 2; k++) b[k] = 0.0f;
#pragma unroll
    for (int k = 0; k <= D; k++) {
        float vs = __fmul_rn(__fsub_rn(elev[k], rem0[k]), downf);
        int idx = D - rnk[k];
        b[idx]     = __fadd_rn(b[idx], vs);
        b[idx + 1] = __fsub_rn(b[idx + 1], vs);
    }
    b[0] = __fadd_rn(b[0], __fadd_rn(1.0f, b[D + 1]));

    int remi[D + 1];
#pragma unroll
    for (int k = 0; k <= D; k++) remi[k] = (int)rem0[k];

#pragma unroll
    for (int m = 0; m <= D; m++) {
        unsigned long long key = 0ull;
#pragma unroll
        for (int j = 0; j < D; j++) {
            int r  = rnk[j];
            int cm = (r < D + 1 - m) ? m : m - (D + 1);
            int c  = remi[j] + cm;
            key |= ((unsigned long long)((unsigned)(c + KBIAS<D>()) & KMASK<D>())) << (KBITS<D>() * j);
        }
        int slot = insert_slot<D>(key, bkt);
        OFFA<D>()[n * (D + 1) + m] = slot;
        WSA<D>()[n * (D + 1) + m]  = b[m];
    }
}

// exclusive scan of both histograms; leaves running bases for k_assign
__global__ void k_scan() {
    __shared__ int sh[NBKT];
    int t = threadIdx.x;
    int v0 = g_hist[t];
    sh[t] = v0; __syncthreads();
#pragma unroll
    for (int o = 1; o < NBKT; o <<= 1) {
        int v = (t >= o) ? sh[t - o] : 0; __syncthreads();
        sh[t] += v; __syncthreads();
    }
    g_hist[t] = sh[t] - v0;            // exclusive base
    if (t == NBKT - 1) g_bi_cnt = sh[NBKT - 1];
    __syncthreads();
    int v1 = g_hist[NBKT + t];
    sh[t] = v1; __syncthreads();
#pragma unroll
    for (int o = 1; o < NBKT; o <<= 1) {
        int v = (t >= o) ? sh[t - o] : 0; __syncthreads();
        sh[t] += v; __syncthreads();
    }
    g_hist[NBKT + t] = sh[t] - v1;
    if (t == NBKT - 1) g_sp_cnt = sh[NBKT - 1];
}

// assign bucketed dense ids; embed in hash high bits; fill key list; zero splat targets
__global__ void k_assign() {
    int i = blockIdx.x * blockDim.x + threadIdx.x;
    if (i < BI_CAP) {
        unsigned long long k = g_bi_hk[i];
        if (k != KEMPTY) {
            int id = atomicAdd(&g_hist[g_bi_bkt[i]], 1);
            g_bi_hk[i] = k | ((unsigned long long)id << 40);
            g_bi_kl[id] = k;
            g_bi_nA[id] = 0.0f;
            ((float4*)g_bi_vC)[id] = make_float4(0, 0, 0, 0);
        }
    } else {
        int j = i - BI_CAP;
        if (j < SP_CAP) {
            unsigned long long k = g_sp_hk[j];
            if (k != KEMPTY) {
                int id = atomicAdd(&g_hist[NBKT + g_sp_bkt[j]], 1);
                g_sp_hk[j] = k | ((unsigned long long)id << 40);
                g_sp_kl[id] = k;
                g_sp_nA[id] = 0.0f;
                ((float4*)g_sp_vC)[id] = make_float4(0, 0, 0, 0);
            }
        }
    }
}

// slot -> dense id for both lattices
__global__ void k_fixoff() {
    int i = blockIdx.x * blockDim.x + threadIdx.x;
    if (i < BI_MMAX) g_bi_off[i] = (int)(g_bi_hk[g_bi_off[i]] >> 40);
    else { int k = i - BI_MMAX; if (k < SP_MMAX) g_sp_off[k] = (int)(g_sp_hk[g_sp_off[k]] >> 40); }
}

template<int D>
__global__ void k_neigh() {
    int i = blockIdx.x * blockDim.x + threadIdx.x;
    if (i >= *CNT<D>()) return;
    unsigned long long key = KL<D>()[i];
    int c[D];
#pragma unroll
    for (int j = 0; j < D; j++) c[j] = (int)((key >> (KBITS<D>() * j)) & KMASK<D>()) - KBIAS<D>();
#pragma unroll
    for (int j = 0; j <= D; j++) {
        unsigned long long k1 = 0ull, k2 = 0ull;
#pragma unroll
        for (int t = 0; t < D; t++) {
            int add = (j < D && t == j) ? (D + 1) : 0;
            int c1 = c[t] - 1 + add;
            int c2 = c[t] + 1 - add;
            k1 |= ((unsigned long long)((unsigned)(c1 + KBIAS<D>()) & KMASK<D>())) << (KBITS<D>() * t);
            k2 |= ((unsigned long long)((unsigned)(c2 + KBIAS<D>()) & KMASK<D>())) << (KBITS<D>() * t);
        }
        ((int2*)BNA<D>())[j * MMAXC<D>() + i] = make_int2(find_id<D>(k1), find_id<D>(k2));
    }
}

// initial Q = softmax(logits); splat Q into vC and splat weights into nA (norm)
__global__ void k_initQ(const float* __restrict__ logits) {
    int n = blockIdx.x * blockDim.x + threadIdx.x;
    if (n >= NPIX) return;
    float4 lg = ((const float4*)logits)[n];
    float mx = fmaxf(fmaxf(lg.x, lg.y), fmaxf(lg.z, lg.w));
    float e0 = expf(lg.x - mx), e1 = expf(lg.y - mx), e2 = expf(lg.z - mx), e3 = expf(lg.w - mx);
    float inv = 1.0f / (e0 + e1 + e2 + e3);
    float q0 = e0 * inv, q1 = e1 * inv, q2 = e2 * inv, q3 = e3 * inv;
#pragma unroll
    for (int m = 0; m <= DBI; m++) {
        int id  = g_bi_off[n * (DBI + 1) + m];
        float w = g_bi_ws[n * (DBI + 1) + m];
        red4(&g_bi_vC[id * 4], w * q0, w * q1, w * q2, w * q3);
        red1(&g_bi_nA[id], w);
    }
#pragma unroll
    for (int m = 0; m <= DSP; m++) {
        int id  = g_sp_off[n * (DSP + 1) + m];
        float w = g_sp_ws[n * (DSP + 1) + m];
        red4(&g_sp_vC[id * 4], w * q0, w * q1, w * q2, w * q3);
        red1(&g_sp_nA[id], w);
    }
}

// blur a pair of points (i, i+1), i even. C=4: values only; C=5: values + norm channel
template<int D, int C, bool CLR>
DEVF void blur_pair(int i, int inb, int outb, const int2* __restrict__ bnA) {
    int cnt = *CNT<D>();
    if (i >= cnt) return;
    int4 nbp = *(const int4*)(bnA + i);          // neighbors of i (x,y) and i+1 (z,w)
    bool two = (i + 1 < cnt);
    {
        const float4* in = (const float4*)VBUF<D>(inb);
        float4* outp = (float4*)VBUF<D>(outb);
        float4 v0 = in[i];
        float4 a0 = make_float4(0, 0, 0, 0), b0 = a0;
        if (nbp.x >= 0) a0 = in[nbp.x];
        if (nbp.y >= 0) b0 = in[nbp.y];
        v0.x += 0.5f * (a0.x + b0.x); v0.y += 0.5f * (a0.y + b0.y);
        v0.z += 0.5f * (a0.z + b0.z); v0.w += 0.5f * (a0.w + b0.w);
        outp[i] = v0;
        if (two) {
            float4 v1 = in[i + 1];
            float4 a1 = make_float4(0, 0, 0, 0), b1 = a1;
            if (nbp.z >= 0) a1 = in[nbp.z];
            if (nbp.w >= 0) b1 = in[nbp.w];
            v1.x += 0.5f * (a1.x + b1.x); v1.y += 0.5f * (a1.y + b1.y);
            v1.z += 0.5f * (a1.z + b1.z); v1.w += 0.5f * (a1.w + b1.w);
            outp[i + 1] = v1;
        }
        if (CLR) {
            float4* cb = (float4*)VBUF<D>(2);
            cb[i] = make_float4(0, 0, 0, 0);
            if (two) cb[i + 1] = make_float4(0, 0, 0, 0);
        }
    }
    if (C == 5) {
        int nin = (inb == 2) ? 0 : inb;          // norm splat lives in A, no C buffer
        const float* in = NBUF<D>(nin);
        float* outp = NBUF<D>(outb);
        float s0 = 0.0f;
        if (nbp.x >= 0) s0 += in[nbp.x];
        if (nbp.y >= 0) s0 += in[nbp.y];
        outp[i] = in[i] + 0.5f * s0;
        if (two) {
            float s1 = 0.0f;
            if (nbp.z >= 0) s1 += in[nbp.z];
            if (nbp.w >= 0) s1 += in[nbp.w];
            outp[i + 1] = in[i + 1] + 0.5f * s1;
        }
    }
}

// combined blur: bi pairs first, then sp pairs (when axis <= DSP)
template<int C, bool CLR>
__global__ void k_blur(int axis, int inb, int outb) {
    int t = blockIdx.x * blockDim.x + threadIdx.x;
    if (t < BI_PAIRS) {
        blur_pair<DBI, C, CLR>(2 * t, inb, outb, ((const int2*)g_bi_bn) + axis * BI_MMAX);
    } else {
        int k = t - BI_PAIRS;
        if (k < SP_PAIRS)
            blur_pair<DSP, C, CLR>(2 * k, inb, outb, ((const int2*)g_sp_bn) + axis * SP_MMAX);
    }
}

// mean-field update. MODE 0 = first (also slices norm channel and stores norms),
// 1 = middle, 2 = last (writes output, no splat)
template<int MODE>
__global__ void k_update(const float* __restrict__ logits, float* __restrict__ out) {
    int n = blockIdx.x * blockDim.x + threadIdx.x;
    if (n >= NPIX) return;
    const float4* vb = (const float4*)g_bi_vA; // bi after 6 passes (C->B->A->B->A->B->A)
    const float4* vs = (const float4*)g_sp_vB; // sp after 3 passes (C->B->A->B)
    float ab0 = 0, ab1 = 0, ab2 = 0, ab3 = 0, sb = 0;
    float as0 = 0, as1 = 0, as2 = 0, as3 = 0, ss = 0;
    int   bids[DBI + 1]; float bws[DBI + 1];
    int   sids[DSP + 1]; float sws[DSP + 1];
#pragma unroll
    for (int m = 0; m <= DBI; m++) {
        bids[m] = g_bi_off[n * (DBI + 1) + m];
        bws[m]  = g_bi_ws[n * (DBI + 1) + m];
    }
#pragma unroll
    for (int m = 0; m <= DSP; m++) {
        sids[m] = g_sp_off[n * (DSP + 1) + m];
        sws[m]  = g_sp_ws[n * (DSP + 1) + m];
    }
#pragma unroll
    for (int m = 0; m <= DBI; m++) {
        float4 t = vb[bids[m]];
        float w = bws[m];
        ab0 += w * t.x; ab1 += w * t.y; ab2 += w * t.z; ab3 += w * t.w;
        if (MODE == 0) sb += w * g_bi_nA[bids[m]];   // bi norm final in nA
    }
#pragma unroll
    for (int m = 0; m <= DSP; m++) {
        float4 t = vs[sids[m]];
        float w = sws[m];
        as0 += w * t.x; as1 += w * t.y; as2 += w * t.z; as3 += w * t.w;
        if (MODE == 0) ss += w * g_sp_nB[sids[m]];   // sp norm final in nB
    }
    float nb_, ns_;
    if (MODE == 0) {
        nb_ = sb * ALPHA_BI; g_bi_norm[n] = nb_;
        ns_ = ss * ALPHA_SP; g_sp_norm[n] = ns_;
    } else {
        nb_ = g_bi_norm[n];
        ns_ = g_sp_norm[n];
    }
    float fbi = 10.0f * ALPHA_BI / (nb_ + 1e-20f);
    float fsp = 3.0f * ALPHA_SP / (ns_ + 1e-20f);
    float4 lg = ((const float4*)logits)[n];
    float a0 = lg.x + fbi * ab0 + fsp * as0;
    float a1 = lg.y + fbi * ab1 + fsp * as1;
    float a2 = lg.z + fbi * ab2 + fsp * as2;
    float a3 = lg.w + fbi * ab3 + fsp * as3;
    float mx = fmaxf(fmaxf(a0, a1), fmaxf(a2, a3));
    float e0 = expf(a0 - mx), e1 = expf(a1 - mx), e2 = expf(a2 - mx), e3 = expf(a3 - mx);
    float inv = 1.0f / (e0 + e1 + e2 + e3);
    float q0 = e0 * inv, q1 = e1 * inv, q2 = e2 * inv, q3 = e3 * inv;
    if (MODE == 2) {
        ((float4*)out)[n] = make_float4(q0, q1, q2, q3);
    } else {
#pragma unroll
        for (int m = 0; m <= DBI; m++) {
            float w = bws[m];
            red4(&g_bi_vC[bids[m] * 4], w * q0, w * q1, w * q2, w * q3);
        }
#pragma unroll
        for (int m = 0; m <= DSP; m++) {
            float w = sws[m];
            red4(&g_sp_vC[sids[m] * 4], w * q0, w * q1, w * q2, w * q3);
        }
    }
}

// ---------------- launch ----------------
extern "C" void kernel_launch(void* const* d_in, const int* in_sizes, int n_in,
                              void* d_out, int out_size) {
    (void)in_sizes; (void)n_in; (void)out_size;
    const float* x      = (const float*)d_in[0];
    const float* logits = (const float*)d_in[1];
    float* out = (float*)d_out;

    const int B = 256;
    auto g = [](long n) { return (unsigned)((n + 255) / 256); };
    const unsigned G_BOTH   = g(BI_MMAX + SP_MMAX);
    const unsigned G_BI     = g(BI_MMAX);
    const unsigned G_CAPS   = g(BI_CAP + SP_CAP);
    const unsigned G_PAIRS  = g(BI_PAIRS + SP_PAIRS);
    const unsigned G_PAIRSB = g(BI_PAIRS);
    const unsigned G_PIX    = g(NPIX);

    // ---- lattice construction ----
    k_reset<DBI><<<g(BI_CAP), B>>>();
    k_reset<DSP><<<g(SP_CAP), B>>>();
    k_build<DBI><<<G_PIX, B>>>(x);
    k_build<DSP><<<G_PIX, B>>>(x);
    k_scan<<<1, NBKT>>>();
    k_assign<<<G_CAPS, B>>>();
    k_fixoff<<<G_BOTH, B>>>();
    k_neigh<DBI><<<G_BI, B>>>();
    k_neigh<DSP><<<g(SP_MMAX), B>>>();

    // ---- init + mean-field iterations (norm fused into iteration 0) ----
    k_initQ<<<G_PIX, B>>>(logits);
    for (int it = 0; it < N_ITER; it++) {
        for (int j = 0; j <= DBI; j++) {
            int inb  = (j == 0) ? 2 : (j & 1);
            int outb = (j & 1) ^ 1;
            unsigned grd = (j <= DSP) ? G_PAIRS : G_PAIRSB;
            if (it == 0) {
                if (j == 1) k_blur<5, true><<<grd, B>>>(j, inb, outb);
                else        k_blur<5, false><<<grd, B>>>(j, inb, outb);
            } else {
                if (j == 1) k_blur<4, true><<<grd, B>>>(j, inb, outb);
                else        k_blur<4, false><<<grd, B>>>(j, inb, outb);
            }
        }
        if (it == 0)
            k_update<0><<<G_PIX, B>>>(logits, out);
        else if (it == N_ITER - 1)
            k_update<2><<<G_PIX, B>>>(logits, out);
        else
            k_update<1><<<G_PIX, B>>>(logits, out);
    }
}

// round 8
// speedup vs baseline: 1.2984x; 1.0699x over previous
#include <cuda_runtime.h>
#include <math.h>

#define DEVF __device__ __forceinline__

// ---------------- problem constants ----------------
constexpr int HH = 512, WW = 512, NPIX = HH * WW, NC = 4;
constexpr int DBI = 5, DSP = 2;
constexpr int N_ITER = 10;

constexpr int BI_CAP = 1 << 22;
constexpr int SP_CAP = 1 << 19;
constexpr int BI_MMAX = NPIX * (DBI + 1); // 1,572,864
constexpr int SP_MMAX = NPIX * (DSP + 1); //   786,432
constexpr int BI_PAIRS = BI_MMAX / 2;
constexpr int SP_PAIRS = SP_MMAX / 2;
constexpr int NBKT = 1024;               // 32x32 tiles of 16x16 pixels
constexpr unsigned long long KEMPTY = ~0ull;
constexpr unsigned long long M40 = (1ull << 40) - 1;
constexpr float ALPHA_BI = 32.0f / 33.0f;
constexpr float ALPHA_SP = 0.8f;

// ---------------- device scratch ----------------
__device__ unsigned long long g_bi_hk[BI_CAP];   // key (40b) | id<<40 after assign
__device__ unsigned long long g_sp_hk[SP_CAP];
__device__ int   g_bi_bkt[BI_CAP];
__device__ int   g_sp_bkt[SP_CAP];
__device__ int   g_hist[2 * NBKT];
__device__ unsigned long long g_bi_kl[BI_MMAX];
__device__ unsigned long long g_sp_kl[SP_MMAX];
// interleaved (id, weight) pairs: .x = bitcast id (slot before fixoff), .y = barycentric w
__device__ __align__(16) float2 g_bi_ow[BI_MMAX];
__device__ __align__(16) float2 g_sp_ow[SP_MMAX];
__device__ __align__(16) int g_bi_bn[(DBI + 1) * BI_MMAX * 2];
__device__ __align__(16) int g_sp_bn[(DSP + 1) * SP_MMAX * 2];
// value buffers: A(0), B(1) ping-pong; C(2) = splat target
__device__ __align__(16) float g_bi_vA[BI_MMAX * NC];
__device__ __align__(16) float g_bi_vB[BI_MMAX * NC];
__device__ __align__(16) float g_bi_vC[BI_MMAX * NC];
__device__ __align__(16) float g_sp_vA[SP_MMAX * NC];
__device__ __align__(16) float g_sp_vB[SP_MMAX * NC];
__device__ __align__(16) float g_sp_vC[SP_MMAX * NC];
__device__ float g_bi_nA[BI_MMAX];
__device__ float g_bi_nB[BI_MMAX];
__device__ float g_sp_nA[SP_MMAX];
__device__ float g_sp_nB[SP_MMAX];
__device__ float g_bi_norm[NPIX];
__device__ float g_sp_norm[NPIX];
__device__ int   g_bi_cnt, g_sp_cnt;

// ---------------- templated accessors ----------------
template<int D> DEVF unsigned long long* HK()  { return D == DBI ? g_bi_hk  : g_sp_hk;  }
template<int D> DEVF int*    BKT() { return D == DBI ? g_bi_bkt : g_sp_bkt; }
template<int D> DEVF unsigned long long* KL()  { return D == DBI ? g_bi_kl  : g_sp_kl;  }
template<int D> DEVF float2* OWA() { return D == DBI ? g_bi_ow  : g_sp_ow;  }
template<int D> DEVF int*    BNA() { return D == DBI ? g_bi_bn  : g_sp_bn;  }
template<int D> DEVF int*    CNT() { return D == DBI ? &g_bi_cnt: &g_sp_cnt;}
template<int D> DEVF int     CAPC(){ return D == DBI ? BI_CAP   : SP_CAP;   }
template<int D> DEVF int     MMAXC(){ return D == DBI ? BI_MMAX : SP_MMAX;  }
template<int D> DEVF int     KBITS(){ return D == DBI ? 8 : 10; }
template<int D> DEVF int     KBIAS(){ return D == DBI ? 128 : 512; }
template<int D> DEVF unsigned KMASK(){ return D == DBI ? 0xFFu : 0x3FFu; }
template<int D> DEVF int     HBASE(){ return D == DBI ? 0 : NBKT; }

template<int D> DEVF float* VBUF(int which) {
    if (D == DBI) return which == 2 ? g_bi_vC : (which ? g_bi_vB : g_bi_vA);
    return which == 2 ? g_sp_vC : (which ? g_sp_vB : g_sp_vA);
}
template<int D> DEVF float* NBUF(int which) {
    return D == DBI ? (which ? g_bi_nB : g_bi_nA) : (which ? g_sp_nB : g_sp_nA);
}

// vectorized float4 reduction (sm_90+)
DEVF void red4(float* p, float a, float b, float c, float d) {
    asm volatile("{ .reg .u64 pg; cvta.to.global.u64 pg, %0; "
                 "red.global.add.v4.f32 [pg], {%1,%2,%3,%4}; }"
                 :: "l"(p), "f"(a), "f"(b), "f"(c), "f"(d) : "memory");
}
DEVF void red1(float* p, float a) {
    asm volatile("{ .reg .u64 pg; cvta.to.global.u64 pg, %0; "
                 "red.global.add.f32 [pg], %1; }"
                 :: "l"(p), "f"(a) : "memory");
}

// ---------------- hash ----------------
DEVF unsigned long long hmix(unsigned long long x) {
    x += 0x9E3779B97F4A7C15ull;
    x = (x ^ (x >> 30)) * 0xBF58476D1CE4E5B9ull;
    x = (x ^ (x >> 27)) * 0x94D049BB133111EBull;
    return x ^ (x >> 31);
}

template<int D>
DEVF int insert_slot(unsigned long long key, int bkt) {
    const unsigned mask = (unsigned)(CAPC<D>() - 1);
    unsigned long long* hk = HK<D>();
    unsigned h = (unsigned)hmix(key) & mask;
    for (;;) {
        unsigned long long prev = atomicCAS(&hk[h], KEMPTY, key);
        if (prev == KEMPTY) {
            BKT<D>()[h] = bkt;
            atomicAdd(&g_hist[HBASE<D>() + bkt], 1);
            return (int)h;
        }
        if (prev == key) return (int)h;
        h = (h + 1) & mask;
    }
}

template<int D>
DEVF int find_id(unsigned long long key) {
    const unsigned mask = (unsigned)(CAPC<D>() - 1);
    const unsigned long long* hk = HK<D>();
    unsigned h = (unsigned)hmix(key) & mask;
    for (;;) {
        unsigned long long v = hk[h];
        if (v == KEMPTY) return -1;
        if ((v & M40) == key) return (int)(v >> 40);
        h = (h + 1) & mask;
    }
}

// ---------------- setup kernels ----------------
template<int D>
__global__ void k_reset() {
    int i = blockIdx.x * blockDim.x + threadIdx.x;
    if (i >= CAPC<D>()) return;
    HK<D>()[i] = KEMPTY;
    if (D == DBI && i < 2 * NBKT) g_hist[i] = 0;
}

template<int D>
__global__ void k_build(const float* __restrict__ x) {
    int n = blockIdx.x * blockDim.x + threadIdx.x;
    if (n >= NPIX) return;
    int py = n / WW, px = n - py * WW;
    int bkt = ((py >> 4) << 5) | (px >> 4);

    float fs[D];
    const double inv_std = sqrt(2.0 / 3.0) * (D + 1);
#pragma unroll
    for (int j = 0; j < D; j++) {
        float f;
        if (D == DBI) {
            if (j == 0)      f = __fdiv_rn((float)px, 80.0f);
            else if (j == 1) f = __fdiv_rn((float)py, 80.0f);
            else             f = __fdiv_rn(x[n * 7 + (6 - j)], 0.0625f);
        } else {
            f = __fdiv_rn((float)(j == 0 ? px : py), 3.0f);
        }
        float sc = (float)(1.0 / sqrt((j + 2.0) * (j + 1.0)) * inv_std);
        fs[j] = __fmul_rn(f, sc);
    }

    float elev[D + 1];
#pragma unroll
    for (int r = 0; r <= D; r++) {
        float s = 0.0f;
#pragma unroll
        for (int j = 0; j < D; j++) {
            float e = (r == 0) ? 1.0f : ((j == r - 1) ? -(float)r : (j >= r ? 1.0f : 0.0f));
            s = __fadd_rn(s, __fmul_rn(e, fs[j]));
        }
        elev[r] = s;
    }

    const float downf = __fdiv_rn(1.0f, (float)(D + 1));
    const float upf = (float)(D + 1);

    float rem0[D + 1], diff[D + 1];
    int   rnk[D + 1];
#pragma unroll
    for (int k = 0; k <= D; k++) {
        float v   = __fmul_rn(elev[k], downf);
        float upr = __fmul_rn(ceilf(v),  upf);
        float dnr = __fmul_rn(floorf(v), upf);
        rem0[k] = (__fsub_rn(upr, elev[k]) < __fsub_rn(elev[k], dnr)) ? upr : dnr;
    }
    float ssum = 0.0f;
#pragma unroll
    for (int k = 0; k <= D; k++) ssum = __fadd_rn(ssum, rem0[k]);
    int s = (int)__fmul_rn(ssum, downf);

#pragma unroll
    for (int k = 0; k <= D; k++) diff[k] = __fsub_rn(elev[k], rem0[k]);
#pragma unroll
    for (int k = 0; k <= D; k++) {
        int r = s;
#pragma unroll
        for (int j = 0; j <= D; j++) {
            if (j > k)      r += (diff[k] <  diff[j]);
            else if (j < k) r += (diff[j] >= diff[k]);
        }
        rnk[k] = r;
    }
#pragma unroll
    for (int k = 0; k <= D; k++) {
        if (rnk[k] < 0)      { rnk[k] += D + 1; rem0[k] = __fadd_rn(rem0[k], upf); }
        else if (rnk[k] > D) { rnk[k] -= D + 1; rem0[k] = __fsub_rn(rem0[k], upf); }
    }

    float b[D + 2];
#pragma unroll
    for (int k = 0; k < D + 2; k++) b[k] = 0.0f;
#pragma unroll
    for (int k = 0; k <= D; k++) {
        float vs = __fmul_rn(__fsub_rn(elev[k], rem0[k]), downf);
        int idx = D - rnk[k];
        b[idx]     = __fadd_rn(b[idx], vs);
        b[idx + 1] = __fsub_rn(b[idx + 1], vs);
    }
    b[0] = __fadd_rn(b[0], __fadd_rn(1.0f, b[D + 1]));

    int remi[D + 1];
#pragma unroll
    for (int k = 0; k <= D; k++) remi[k] = (int)rem0[k];

#pragma unroll
    for (int m = 0; m <= D; m++) {
        unsigned long long key = 0ull;
#pragma unroll
        for (int j = 0; j < D; j++) {
            int r  = rnk[j];
            int cm = (r < D + 1 - m) ? m : m - (D + 1);
            int c  = remi[j] + cm;
            key |= ((unsigned long long)((unsigned)(c + KBIAS<D>()) & KMASK<D>())) << (KBITS<D>() * j);
        }
        int slot = insert_slot<D>(key, bkt);
        OWA<D>()[n * (D + 1) + m] = make_float2(__int_as_float(slot), b[m]);
    }
}

__global__ void k_scan() {
    __shared__ int sh[NBKT];
    int t = threadIdx.x;
    int v0 = g_hist[t];
    sh[t] = v0; __syncthreads();
#pragma unroll
    for (int o = 1; o < NBKT; o <<= 1) {
        int v = (t >= o) ? sh[t - o] : 0; __syncthreads();
        sh[t] += v; __syncthreads();
    }
    g_hist[t] = sh[t] - v0;
    if (t == NBKT - 1) g_bi_cnt = sh[NBKT - 1];
    __syncthreads();
    int v1 = g_hist[NBKT + t];
    sh[t] = v1; __syncthreads();
#pragma unroll
    for (int o = 1; o < NBKT; o <<= 1) {
        int v = (t >= o) ? sh[t - o] : 0; __syncthreads();
        sh[t] += v; __syncthreads();
    }
    g_hist[NBKT + t] = sh[t] - v1;
    if (t == NBKT - 1) g_sp_cnt = sh[NBKT - 1];
}

__global__ void k_assign() {
    int i = blockIdx.x * blockDim.x + threadIdx.x;
    if (i < BI_CAP) {
        unsigned long long k = g_bi_hk[i];
        if (k != KEMPTY) {
            int id = atomicAdd(&g_hist[g_bi_bkt[i]], 1);
            g_bi_hk[i] = k | ((unsigned long long)id << 40);
            g_bi_kl[id] = k;
            g_bi_nA[id] = 0.0f;
            ((float4*)g_bi_vC)[id] = make_float4(0, 0, 0, 0);
        }
    } else {
        int j = i - BI_CAP;
        if (j < SP_CAP) {
            unsigned long long k = g_sp_hk[j];
            if (k != KEMPTY) {
                int id = atomicAdd(&g_hist[NBKT + g_sp_bkt[j]], 1);
                g_sp_hk[j] = k | ((unsigned long long)id << 40);
                g_sp_kl[id] = k;
                g_sp_nA[id] = 0.0f;
                ((float4*)g_sp_vC)[id] = make_float4(0, 0, 0, 0);
            }
        }
    }
}

__global__ void k_fixoff() {
    int i = blockIdx.x * blockDim.x + threadIdx.x;
    if (i < BI_MMAX) {
        int slot = __float_as_int(g_bi_ow[i].x);
        g_bi_ow[i].x = __int_as_float((int)(g_bi_hk[slot] >> 40));
    } else {
        int k = i - BI_MMAX;
        if (k < SP_MMAX) {
            int slot = __float_as_int(g_sp_ow[k].x);
            g_sp_ow[k].x = __int_as_float((int)(g_sp_hk[slot] >> 40));
        }
    }
}

template<int D>
__global__ void k_neigh() {
    int i = blockIdx.x * blockDim.x + threadIdx.x;
    if (i >= *CNT<D>()) return;
    unsigned long long key = KL<D>()[i];
    int c[D];
#pragma unroll
    for (int j = 0; j < D; j++) c[j] = (int)((key >> (KBITS<D>() * j)) & KMASK<D>()) - KBIAS<D>();
#pragma unroll
    for (int j = 0; j <= D; j++) {
        unsigned long long k1 = 0ull, k2 = 0ull;
#pragma unroll
        for (int t = 0; t < D; t++) {
            int add = (j < D && t == j) ? (D + 1) : 0;
            int c1 = c[t] - 1 + add;
            int c2 = c[t] + 1 - add;
            k1 |= ((unsigned long long)((unsigned)(c1 + KBIAS<D>()) & KMASK<D>())) << (KBITS<D>() * t);
            k2 |= ((unsigned long long)((unsigned)(c2 + KBIAS<D>()) & KMASK<D>())) << (KBITS<D>() * t);
        }
        ((int2*)BNA<D>())[j * MMAXC<D>() + i] = make_int2(find_id<D>(k1), find_id<D>(k2));
    }
}

// ---------------- loop kernels (PDL-launched) ----------------

// initial Q = softmax(logits); splat Q into vC and ones into nA
__global__ void k_initQ(const float* __restrict__ logits) {
    int n = blockIdx.x * blockDim.x + threadIdx.x;
    if (n >= NPIX) return;
    float4 lg = ((const float4*)logits)[n];
    float2 bow[DBI + 1], sow[DSP + 1];
#pragma unroll
    for (int m = 0; m <= DBI; m++) bow[m] = g_bi_ow[n * (DBI + 1) + m];
#pragma unroll
    for (int m = 0; m <= DSP; m++) sow[m] = g_sp_ow[n * (DSP + 1) + m];
    cudaGridDependencySynchronize();
    float mx = fmaxf(fmaxf(lg.x, lg.y), fmaxf(lg.z, lg.w));
    float e0 = expf(lg.x - mx), e1 = expf(lg.y - mx), e2 = expf(lg.z - mx), e3 = expf(lg.w - mx);
    float inv = 1.0f / (e0 + e1 + e2 + e3);
    float q0 = e0 * inv, q1 = e1 * inv, q2 = e2 * inv, q3 = e3 * inv;
#pragma unroll
    for (int m = 0; m <= DBI; m++) {
        int id = __float_as_int(bow[m].x);
        float w = bow[m].y;
        red4(&g_bi_vC[id * 4], w * q0, w * q1, w * q2, w * q3);
        red1(&g_bi_nA[id], w);
    }
#pragma unroll
    for (int m = 0; m <= DSP; m++) {
        int id = __float_as_int(sow[m].x);
        float w = sow[m].y;
        red4(&g_sp_vC[id * 4], w * q0, w * q1, w * q2, w * q3);
        red1(&g_sp_nA[id], w);
    }
}

// value-blur of a pair (i, i+1); nbp preloaded
template<int D, int C, bool CLR>
DEVF void blur_vals(int i, int cnt, int4 nbp, int inb, int outb) {
    bool two = (i + 1 < cnt);
    {
        const float4* in = (const float4*)VBUF<D>(inb);
        float4* outp = (float4*)VBUF<D>(outb);
        float4 v0 = in[i];
        float4 a0 = make_float4(0, 0, 0, 0), b0 = a0;
        if (nbp.x >= 0) a0 = in[nbp.x];
        if (nbp.y >= 0) b0 = in[nbp.y];
        v0.x += 0.5f * (a0.x + b0.x); v0.y += 0.5f * (a0.y + b0.y);
        v0.z += 0.5f * (a0.z + b0.z); v0.w += 0.5f * (a0.w + b0.w);
        outp[i] = v0;
        if (two) {
            float4 v1 = in[i + 1];
            float4 a1 = make_float4(0, 0, 0, 0), b1 = a1;
            if (nbp.z >= 0) a1 = in[nbp.z];
            if (nbp.w >= 0) b1 = in[nbp.w];
            v1.x += 0.5f * (a1.x + b1.x); v1.y += 0.5f * (a1.y + b1.y);
            v1.z += 0.5f * (a1.z + b1.z); v1.w += 0.5f * (a1.w + b1.w);
            outp[i + 1] = v1;
        }
        if (CLR) {
            float4* cb = (float4*)VBUF<D>(2);
            cb[i] = make_float4(0, 0, 0, 0);
            if (two) cb[i + 1] = make_float4(0, 0, 0, 0);
        }
    }
    if (C == 5) {
        int nin = (inb == 2) ? 0 : inb;
        const float* in = NBUF<D>(nin);
        float* outp = NBUF<D>(outb);
        float s0 = 0.0f;
        if (nbp.x >= 0) s0 += in[nbp.x];
        if (nbp.y >= 0) s0 += in[nbp.y];
        outp[i] = in[i] + 0.5f * s0;
        if (two) {
            float s1 = 0.0f;
            if (nbp.z >= 0) s1 += in[nbp.z];
            if (nbp.w >= 0) s1 += in[nbp.w];
            outp[i + 1] = in[i + 1] + 0.5f * s1;
        }
    }
}

template<int C, bool CLR>
__global__ void k_blur(int axis, int inb, int outb) {
    int t = blockIdx.x * blockDim.x + threadIdx.x;
    // static prologue: counts + neighbor indices (written in setup, constant in loop)
    if (t < BI_PAIRS) {
        int i = 2 * t;
        int cnt = g_bi_cnt;
        if (i >= cnt) { cudaGridDependencySynchronize(); return; }
        int4 nbp = *(const int4*)(((const int2*)g_bi_bn) + axis * BI_MMAX + i);
        cudaGridDependencySynchronize();
        blur_vals<DBI, C, CLR>(i, cnt, nbp, inb, outb);
    } else {
        int k = t - BI_PAIRS;
        if (k >= SP_PAIRS) { cudaGridDependencySynchronize(); return; }
        int i = 2 * k;
        int cnt = g_sp_cnt;
        if (i >= cnt) { cudaGridDependencySynchronize(); return; }
        int4 nbp = *(const int4*)(((const int2*)g_sp_bn) + axis * SP_MMAX + i);
        cudaGridDependencySynchronize();
        blur_vals<DSP, C, CLR>(i, cnt, nbp, inb, outb);
    }
}

// mean-field update. MODE 0 = first (slices norm channel, stores norms),
// 1 = middle, 2 = last (writes output, no splat)
template<int MODE>
__global__ void k_update(const float* __restrict__ logits, float* __restrict__ out) {
    int n = blockIdx.x * blockDim.x + threadIdx.x;
    if (n >= NPIX) { cudaGridDependencySynchronize(); return; }
    // static prologue
    float2 bow[DBI + 1], sow[DSP + 1];
#pragma unroll
    for (int m = 0; m <= DBI; m++) bow[m] = g_bi_ow[n * (DBI + 1) + m];
#pragma unroll
    for (int m = 0; m <= DSP; m++) sow[m] = g_sp_ow[n * (DSP + 1) + m];
    float4 lg = ((const float4*)logits)[n];
    float nb_ = 0, ns_ = 0;
    if (MODE != 0) { nb_ = g_bi_norm[n]; ns_ = g_sp_norm[n]; }
    cudaGridDependencySynchronize();

    const float4* vb = (const float4*)g_bi_vA; // bi after 6 passes (C->B->A->B->A->B->A)
    const float4* vs = (const float4*)g_sp_vB; // sp after 3 passes (C->B->A->B)
    float ab0 = 0, ab1 = 0, ab2 = 0, ab3 = 0, sb = 0;
    float as0 = 0, as1 = 0, as2 = 0, as3 = 0, ss = 0;
#pragma unroll
    for (int m = 0; m <= DBI; m++) {
        int id = __float_as_int(bow[m].x);
        float w = bow[m].y;
        float4 t = vb[id];
        ab0 += w * t.x; ab1 += w * t.y; ab2 += w * t.z; ab3 += w * t.w;
        if (MODE == 0) sb += w * g_bi_nA[id];
    }
#pragma unroll
    for (int m = 0; m <= DSP; m++) {
        int id = __float_as_int(sow[m].x);
        float w = sow[m].y;
        float4 t = vs[id];
        as0 += w * t.x; as1 += w * t.y; as2 += w * t.z; as3 += w * t.w;
        if (MODE == 0) ss += w * g_sp_nB[id];
    }
    if (MODE == 0) {
        nb_ = sb * ALPHA_BI; g_bi_norm[n] = nb_;
        ns_ = ss * ALPHA_SP; g_sp_norm[n] = ns_;
    }
    float fbi = 10.0f * ALPHA_BI / (nb_ + 1e-20f);
    float fsp = 3.0f * ALPHA_SP / (ns_ + 1e-20f);
    float a0 = lg.x + fbi * ab0 + fsp * as0;
    float a1 = lg.y + fbi * ab1 + fsp * as1;
    float a2 = lg.z + fbi * ab2 + fsp * as2;
    float a3 = lg.w + fbi * ab3 + fsp * as3;
    float mx = fmaxf(fmaxf(a0, a1), fmaxf(a2, a3));
    float e0 = expf(a0 - mx), e1 = expf(a1 - mx), e2 = expf(a2 - mx), e3 = expf(a3 - mx);
    float inv = 1.0f / (e0 + e1 + e2 + e3);
    float q0 = e0 * inv, q1 = e1 * inv, q2 = e2 * inv, q3 = e3 * inv;
    if (MODE == 2) {
        ((float4*)out)[n] = make_float4(q0, q1, q2, q3);
    } else {
#pragma unroll
        for (int m = 0; m <= DBI; m++) {
            int id = __float_as_int(bow[m].x);
            float w = bow[m].y;
            red4(&g_bi_vC[id * 4], w * q0, w * q1, w * q2, w * q3);
        }
#pragma unroll
        for (int m = 0; m <= DSP; m++) {
            int id = __float_as_int(sow[m].x);
            float w = sow[m].y;
            red4(&g_sp_vC[id * 4], w * q0, w * q1, w * q2, w * q3);
        }
    }
}

// ---------------- launch ----------------
template<typename K, typename... Args>
static void launch_pdl(unsigned grid, unsigned block, K kernel, Args... args) {
    cudaLaunchConfig_t cfg = {};
    cfg.gridDim = dim3(grid, 1, 1);
    cfg.blockDim = dim3(block, 1, 1);
    cfg.dynamicSmemBytes = 0;
    cfg.stream = 0;
    cudaLaunchAttribute at[1];
    at[0].id = cudaLaunchAttributeProgrammaticStreamSerialization;
    at[0].val.programmaticStreamSerializationAllowed = 1;
    cfg.attrs = at;
    cfg.numAttrs = 1;
    cudaLaunchKernelEx(&cfg, kernel, args...);
}

extern "C" void kernel_launch(void* const* d_in, const int* in_sizes, int n_in,
                              void* d_out, int out_size) {
    (void)in_sizes; (void)n_in; (void)out_size;
    const float* x      = (const float*)d_in[0];
    const float* logits = (const float*)d_in[1];
    float* out = (float*)d_out;

    const int B = 256;
    auto g = [](long n) { return (unsigned)((n + 255) / 256); };
    const unsigned G_BOTH   = g(BI_MMAX + SP_MMAX);
    const unsigned G_BI     = g(BI_MMAX);
    const unsigned G_CAPS   = g(BI_CAP + SP_CAP);
    const unsigned G_PAIRS  = g(BI_PAIRS + SP_PAIRS);
    const unsigned G_PAIRSB = g(BI_PAIRS);
    const unsigned G_PIX    = g(NPIX);

    // ---- lattice construction (normal launches) ----
    k_reset<DBI><<<g(BI_CAP), B>>>();
    k_reset<DSP><<<g(SP_CAP), B>>>();
    k_build<DBI><<<G_PIX, B>>>(x);
    k_build<DSP><<<G_PIX, B>>>(x);
    k_scan<<<1, NBKT>>>();
    k_assign<<<G_CAPS, B>>>();
    k_fixoff<<<G_BOTH, B>>>();
    k_neigh<DBI><<<G_BI, B>>>();
    k_neigh<DSP><<<g(SP_MMAX), B>>>();

    // ---- init + mean-field iterations (PDL chain; norm fused into iteration 0) ----
    k_initQ<<<G_PIX, B>>>(logits);
    for (int it = 0; it < N_ITER; it++) {
        for (int j = 0; j <= DBI; j++) {
            int inb  = (j == 0) ? 2 : (j & 1);
            int outb = (j & 1) ^ 1;
            unsigned grd = (j <= DSP) ? G_PAIRS : G_PAIRSB;
            if (it == 0) {
                if (j == 1) launch_pdl(grd, B, k_blur<5, true>,  j, inb, outb);
                else        launch_pdl(grd, B, k_blur<5, false>, j, inb, outb);
            } else {
                if (j == 1) launch_pdl(grd, B, k_blur<4, true>,  j, inb, outb);
                else        launch_pdl(grd, B, k_blur<4, false>, j, inb, outb);
            }
        }
        if (it == 0)
            launch_pdl(G_PIX, B, k_update<0>, logits, out);
        else if (it == N_ITER - 1)
            launch_pdl(G_PIX, B, k_update<2>, logits, out);
        else
            launch_pdl(G_PIX, B, k_update<1>, logits, out);
    }
}